// round 7
// baseline (speedup 1.0000x reference)
#include <cuda_runtime.h>
#include <cuda_bf16.h>

#define BATCH 4
#define SEQ   1024
#define DM    1024
#define HEADS 16
#define HD    64
#define BH    (BATCH*HEADS)

// ---------------- scratch (device globals; no allocs allowed) ----------------
__device__ float g_Q[BATCH*SEQ*DM];   // 16 MB
__device__ float g_K[BATCH*SEQ*DM];   // 16 MB
__device__ float g_V[BATCH*SEQ*DM];   // 16 MB
__device__ float g_O[BATCH*SEQ*DM];   // 16 MB

// ---------------- helpers ----------------
__device__ __forceinline__ void split2(float2 v, unsigned &h, unsigned &l) {
    __nv_bfloat162 bh = __float22bfloat162_rn(v);
    float2 back = __bfloat1622float2(bh);
    __nv_bfloat162 bl = __float22bfloat162_rn(make_float2(v.x - back.x, v.y - back.y));
    h = *(unsigned*)&bh;
    l = *(unsigned*)&bl;
}

__device__ __forceinline__ void mma_bf16(float c[4], const unsigned a[4], const unsigned b[2]) {
    asm volatile(
        "mma.sync.aligned.m16n8k16.row.col.f32.bf16.bf16.f32 "
        "{%0,%1,%2,%3},{%4,%5,%6,%7},{%8,%9},{%0,%1,%2,%3};\n"
        : "+f"(c[0]), "+f"(c[1]), "+f"(c[2]), "+f"(c[3])
        : "r"(a[0]), "r"(a[1]), "r"(a[2]), "r"(a[3]), "r"(b[0]), "r"(b[1]));
}

// store 16 consecutive k floats (row-major) as 8 packed bf16 pairs (16B-aligned stores)
template<int P>
__device__ __forceinline__ void st_rm16(const float* src, unsigned (*H)[P], unsigned (*L)[P],
                                        int row, int p0) {
    unsigned h[8], l[8];
    #pragma unroll
    for (int i = 0; i < 4; i++) {
        const float4 x = *(const float4*)(src + 4 * i);
        split2(make_float2(x.x, x.y), h[2 * i], l[2 * i]);
        split2(make_float2(x.z, x.w), h[2 * i + 1], l[2 * i + 1]);
    }
    *(uint4*)&H[row][p0]     = make_uint4(h[0], h[1], h[2], h[3]);
    *(uint4*)&H[row][p0 + 4] = make_uint4(h[4], h[5], h[6], h[7]);
    *(uint4*)&L[row][p0]     = make_uint4(l[0], l[1], l[2], l[3]);
    *(uint4*)&L[row][p0 + 4] = make_uint4(l[4], l[5], l[6], l[7]);
}

template<int P>
__device__ __forceinline__ void st_rm16z(unsigned (*H)[P], unsigned (*L)[P], int row, int p0) {
    const uint4 z = make_uint4(0, 0, 0, 0);
    *(uint4*)&H[row][p0] = z; *(uint4*)&H[row][p0 + 4] = z;
    *(uint4*)&L[row][p0] = z; *(uint4*)&L[row][p0 + 4] = z;
}

// store a 2(k)x4(n) chunk from two k-rows into col-major B operand (scalar stores)
template<int P>
__device__ __forceinline__ void st_km2x4(float4 x0, float4 x1, unsigned (*H)[P],
                                         unsigned (*L)[P], int c, int kp) {
    unsigned h, l;
    split2(make_float2(x0.x, x1.x), h, l); H[c][kp] = h;     L[c][kp] = l;
    split2(make_float2(x0.y, x1.y), h, l); H[c + 1][kp] = h; L[c + 1][kp] = l;
    split2(make_float2(x0.z, x1.z), h, l); H[c + 2][kp] = h; L[c + 2][kp] = l;
    split2(make_float2(x0.w, x1.w), h, l); H[c + 3][kp] = h; L[c + 3][kp] = l;
}

// one k16 slab (pair base pb), TN n8-tiles, 3-term split MMA
template<int TN, int PA, int PB>
__device__ __forceinline__ void mma_k16_3(float (*acc)[4],
    const unsigned (*Ah)[PA], const unsigned (*Al)[PA],
    const unsigned (*Bh)[PB], const unsigned (*Bl)[PB],
    int arow, int pb, int qr, int qc)
{
    unsigned ah[4] = {Ah[arow + qr][pb + qc], Ah[arow + qr + 8][pb + qc],
                      Ah[arow + qr][pb + qc + 4], Ah[arow + qr + 8][pb + qc + 4]};
    unsigned al[4] = {Al[arow + qr][pb + qc], Al[arow + qr + 8][pb + qc],
                      Al[arow + qr][pb + qc + 4], Al[arow + qr + 8][pb + qc + 4]};
    #pragma unroll
    for (int tn = 0; tn < TN; tn++) {
        const int n = tn * 8 + qr;
        unsigned bh2[2] = {Bh[n][pb + qc], Bh[n][pb + qc + 4]};
        unsigned bl2[2] = {Bl[n][pb + qc], Bl[n][pb + qc + 4]};
        mma_bf16(acc[tn], ah, bh2);
        mma_bf16(acc[tn], al, bh2);
        mma_bf16(acc[tn], ah, bl2);
    }
}

__device__ __forceinline__ const float* q_row(int b, int h, int i) {
    return g_Q + (size_t)(b * SEQ + h * HD + (i >> 4)) * DM + ((i & 15) << 6);
}
__device__ __forceinline__ const float* v_row(int b, int h, int j) {
    return g_V + (size_t)(b * SEQ + h * HD + (j >> 4)) * DM + ((j & 15) << 6);
}

// ==================== projection / merge GEMM (round-3 proven) ====================
__device__ __forceinline__ void mma32p(const unsigned (*Ah)[20], const unsigned (*Al)[20],
                                       const unsigned (*Bh)[20], const unsigned (*Bl)[20],
                                       float (*acc)[4][4], int warp_m, int warp_n, int lane) {
    const int qr = lane >> 2, qc = lane & 3;
    #pragma unroll
    for (int s = 0; s < 2; s++) {
        const int kp = qc + 8 * s;
        unsigned ah[4][4], al[4][4], bh[4][2], bl[4][2];
        #pragma unroll
        for (int tm = 0; tm < 4; tm++) {
            const int m = warp_m + tm * 16 + qr;
            ah[tm][0] = Ah[m][kp];     ah[tm][1] = Ah[m + 8][kp];
            ah[tm][2] = Ah[m][kp + 4]; ah[tm][3] = Ah[m + 8][kp + 4];
            al[tm][0] = Al[m][kp];     al[tm][1] = Al[m + 8][kp];
            al[tm][2] = Al[m][kp + 4]; al[tm][3] = Al[m + 8][kp + 4];
        }
        #pragma unroll
        for (int tn = 0; tn < 4; tn++) {
            const int n = warp_n + tn * 8 + qr;
            bh[tn][0] = Bh[n][kp]; bh[tn][1] = Bh[n][kp + 4];
            bl[tn][0] = Bl[n][kp]; bl[tn][1] = Bl[n][kp + 4];
        }
        #pragma unroll
        for (int tm = 0; tm < 4; tm++)
            #pragma unroll
            for (int tn = 0; tn < 4; tn++) {
                mma_bf16(acc[tm][tn], ah[tm], bh[tn]);
                mma_bf16(acc[tm][tn], al[tm], bh[tn]);
                mma_bf16(acc[tm][tn], ah[tm], bl[tn]);
            }
    }
}

__global__ __launch_bounds__(256, 2) void bf_gemm_nn(const float* __restrict__ A,
                                                     const float* __restrict__ W,
                                                     float* __restrict__ C,
                                                     int M, int N, int K)
{
    __shared__ unsigned Ah[128][20], Al[128][20], Bh[128][20], Bl[128][20];
    const int tid = threadIdx.x, lane = tid & 31, w = tid >> 5;
    const int m0 = blockIdx.y << 7, n0 = blockIdx.x << 7;
    const int warp_m = (w >> 2) * 64, warp_n = (w & 3) * 32;
    const int am = tid >> 1, ako = (tid & 1) << 4;
    const int bkp = tid & 15, bcg = tid >> 4;
    float acc[4][4][4] = {};

    for (int k0 = 0; k0 < K; k0 += 32) {
        st_rm16<20>(A + (size_t)(m0 + am) * K + k0 + ako, Ah, Al, am, ako >> 1);
        #pragma unroll
        for (int rep = 0; rep < 2; rep++) {
            const int c = (bcg + 16 * rep) << 2;
            const float* p = W + (size_t)(k0 + 2 * bkp) * N + n0 + c;
            st_km2x4<20>(*(const float4*)p, *(const float4*)(p + N), Bh, Bl, c, bkp);
        }
        __syncthreads();
        mma32p(Ah, Al, Bh, Bl, acc, warp_m, warp_n, lane);
        __syncthreads();
    }
    const int qr = lane >> 2, qc = lane & 3;
    #pragma unroll
    for (int tm = 0; tm < 4; tm++)
        #pragma unroll
        for (int tn = 0; tn < 4; tn++) {
            const int r = m0 + warp_m + tm * 16 + qr;
            const int cN = n0 + warp_n + tn * 8 + qc * 2;
            *(float2*)(C + (size_t)r * N + cN)       = make_float2(acc[tm][tn][0], acc[tm][tn][1]);
            *(float2*)(C + (size_t)(r + 8) * N + cN) = make_float2(acc[tm][tn][2], acc[tm][tn][3]);
        }
}

// ==================== fused flash attention with relative bias (512 threads) ====================
struct FSmem {
    unsigned Qh[129][36], Ql[129][36];   // Q rows i0..i0+128 (129 for the +1 shift)
    unsigned Kh[128][36], Kl[128][36];   // K^T tile: [j][dd-pair]
    unsigned Eh[128][36], El[128][36];   // Er window: [e][dd-pair]
    unsigned Vh[64][68],  Vl[64][68];    // V tile: [dd][j-pair]
    union {
        float G[128][132];                        // rel-bias staging
        struct { unsigned Ph[128][68], Pl[128][68]; } pp;  // softmaxed P operand
    } u;
    float redmax[128][2];                 // cross-warp softmax staging
    float redsum[128][2];
};

__global__ __launch_bounds__(512, 1) void flash_kernel(const float* __restrict__ Er)
{
    extern __shared__ char raw[];
    FSmem* sm = (FSmem*)raw;
    const int tid = threadIdx.x, lane = tid & 31, w = tid >> 5;   // 16 warps
    const int qr = lane >> 2, qc = lane & 3;
    const int rg = w & 7, cg = w >> 3;        // row-group (16 rows), col-group (64 cols)
    const int rg16 = rg << 4;
    const int bh = blockIdx.y, b = bh >> 4, h = bh & 15;
    const int i0 = blockIdx.x << 7;

    // ---- load Q: 129 rows x 4 chunks of 16 floats ----
    #pragma unroll
    for (int it = 0; it < 2; it++) {
        const int idx = tid + it * 512;
        if (idx < 129 * 4) {
            const int r = idx >> 2, ch = idx & 3;
            if (i0 + r < SEQ) st_rm16<36>(q_row(b, h, i0 + r) + ch * 16, sm->Qh, sm->Ql, r, ch * 8);
            else              st_rm16z<36>(sm->Qh, sm->Ql, r, ch * 8);
        }
    }

    float accO[4][4] = {};                    // 16 rows x 32 cols per warp
    float m0 = -1e30f, m1 = -1e30f, l0 = 0.f, l1 = 0.f;
    const float* kbase = g_K + (size_t)(b * SEQ + h * HD) * DM;

    for (int jt = 0; jt < 8; jt++) {
        const int j0 = jt << 7;
        const int delta = j0 - i0;
        float accS[8][4] = {};               // 16 rows x 64 cols per warp

        // ---- relative-bias phases: G = Q(+shift) @ ErWindow^T, then diagonal gather ----
        #pragma unroll 1
        for (int band = 0; band < 2; band++) {       // 0 = lower (c<=i), 1 = upper (c>=i+2)
            if (band == 0 && delta > 0) continue;
            if (band == 1 && delta < 0) continue;
            const int ebase = (band == 0) ? (895 + delta) : (delta - 130);
            #pragma unroll 1
            for (int half = 0; half < 2; half++) {
                if (band == 1 && half == 0 && delta < 128) continue;
                {   // load Er window half: exactly 512 chunk-ops
                    const int r = tid >> 2, ch = tid & 3;
                    const int er = ebase + half * 128 + r;
                    if (er >= 0 && er < SEQ)
                        st_rm16<36>(Er + (size_t)er * HD + ch * 16, sm->Eh, sm->El, r, ch * 8);
                    else
                        st_rm16z<36>(sm->Eh, sm->El, r, ch * 8);
                }
                __syncthreads();   // E ready; also frees P/V from prior tile's MMA reads
                const int arow = rg16 + band;        // upper band uses q_{i+1}
                #pragma unroll 1
                for (int nh = 0; nh < 2; nh++) {     // two 32-col halves: gacc stays small
                    float gacc[4][4] = {};
                    const unsigned (*Ehp)[36] = (const unsigned (*)[36])&sm->Eh[cg * 64 + nh * 32];
                    const unsigned (*Elp)[36] = (const unsigned (*)[36])&sm->El[cg * 64 + nh * 32];
                    #pragma unroll
                    for (int pb = 0; pb < 32; pb += 8)
                        mma_k16_3<4, 36, 36>(gacc, sm->Qh, sm->Ql, Ehp, Elp, arow, pb, qr, qc);
                    #pragma unroll
                    for (int tn = 0; tn < 4; tn++) {
                        const int r = rg16 + qr, c = cg * 64 + nh * 32 + tn * 8 + qc * 2;
                        *(float2*)&sm->u.G[r][c]     = make_float2(gacc[tn][0], gacc[tn][1]);
                        *(float2*)&sm->u.G[r + 8][c] = make_float2(gacc[tn][2], gacc[tn][3]);
                    }
                }
                __syncthreads();
                #pragma unroll
                for (int tn = 0; tn < 8; tn++)
                    #pragma unroll
                    for (int k = 0; k < 4; k++) {
                        const int r = rg16 + qr + ((k >> 1) << 3);
                        const int jc = cg * 64 + tn * 8 + qc * 2 + (k & 1);
                        const int diff = jc - r;
                        const bool cond = (band == 0) ? (diff <= -delta) : (diff >= 2 - delta);
                        const int mm = 128 + diff - half * 128;
                        if (cond && mm >= 0 && mm < 128) accS[tn][k] += sm->u.G[r][mm];
                    }
            }
        }

        // ---- load K^T and V tiles (512 threads, 2 iterations each) ----
        #pragma unroll
        for (int it = 0; it < 2; it++) {
            const int idx = tid + it * 512;
            const int kp = idx & 31, cgl = idx >> 5;
            const float* p = kbase + (size_t)(2 * kp) * DM + j0 + cgl * 4;
            st_km2x4<36>(*(const float4*)p, *(const float4*)(p + DM), sm->Kh, sm->Kl, cgl * 4, kp);
        }
        #pragma unroll
        for (int it = 0; it < 2; it++) {
            const int idx = tid + it * 512;
            const int jp = idx & 63, cgl = idx >> 6;
            const float4 x0 = *(const float4*)(v_row(b, h, j0 + 2 * jp)     + cgl * 4);
            const float4 x1 = *(const float4*)(v_row(b, h, j0 + 2 * jp + 1) + cgl * 4);
            st_km2x4<68>(x0, x1, sm->Vh, sm->Vl, cgl * 4, jp);
        }
        __syncthreads();   // K,V ready; all gathers done (G region free for P)

        // ---- q @ k^T accumulate on top of rel (warp: 16 rows x 64 cols) ----
        {
            const unsigned (*Khp)[36] = (const unsigned (*)[36])&sm->Kh[cg * 64];
            const unsigned (*Klp)[36] = (const unsigned (*)[36])&sm->Kl[cg * 64];
            #pragma unroll
            for (int pb = 0; pb < 32; pb += 8)
                mma_k16_3<8, 36, 36>(accS, sm->Qh, sm->Ql, Khp, Klp, rg16, pb, qr, qc);
        }

        // ---- online softmax (logits = accS * 0.125), cross-warp over 2 col groups ----
        float tm0 = -1e30f, tm1 = -1e30f;
        #pragma unroll
        for (int tn = 0; tn < 8; tn++) {
            tm0 = fmaxf(tm0, fmaxf(accS[tn][0], accS[tn][1]));
            tm1 = fmaxf(tm1, fmaxf(accS[tn][2], accS[tn][3]));
        }
        tm0 = fmaxf(tm0, __shfl_xor_sync(0xffffffffu, tm0, 1));
        tm0 = fmaxf(tm0, __shfl_xor_sync(0xffffffffu, tm0, 2));
        tm1 = fmaxf(tm1, __shfl_xor_sync(0xffffffffu, tm1, 1));
        tm1 = fmaxf(tm1, __shfl_xor_sync(0xffffffffu, tm1, 2));
        tm0 *= 0.125f; tm1 *= 0.125f;
        if (qc == 0) {
            sm->redmax[rg16 + qr][cg]     = tm0;
            sm->redmax[rg16 + qr + 8][cg] = tm1;
        }
        __syncthreads();
        const float cm0 = fmaxf(sm->redmax[rg16 + qr][0],     sm->redmax[rg16 + qr][1]);
        const float cm1 = fmaxf(sm->redmax[rg16 + qr + 8][0], sm->redmax[rg16 + qr + 8][1]);
        const float nm0 = fmaxf(m0, cm0), nm1 = fmaxf(m1, cm1);
        const float f0 = __expf(m0 - nm0), f1 = __expf(m1 - nm1);
        float s0 = 0.f, s1 = 0.f;
        #pragma unroll
        for (int tn = 0; tn < 8; tn++) {
            accS[tn][0] = __expf(accS[tn][0] * 0.125f - nm0); s0 += accS[tn][0];
            accS[tn][1] = __expf(accS[tn][1] * 0.125f - nm0); s0 += accS[tn][1];
            accS[tn][2] = __expf(accS[tn][2] * 0.125f - nm1); s1 += accS[tn][2];
            accS[tn][3] = __expf(accS[tn][3] * 0.125f - nm1); s1 += accS[tn][3];
        }
        s0 += __shfl_xor_sync(0xffffffffu, s0, 1); s0 += __shfl_xor_sync(0xffffffffu, s0, 2);
        s1 += __shfl_xor_sync(0xffffffffu, s1, 1); s1 += __shfl_xor_sync(0xffffffffu, s1, 2);
        if (qc == 0) {
            sm->redsum[rg16 + qr][cg]     = s0;
            sm->redsum[rg16 + qr + 8][cg] = s1;
        }

        // ---- write split-bf16 P operand (overlap with sum staging; synced below) ----
        #pragma unroll
        for (int tn = 0; tn < 8; tn++) {
            unsigned hh, ll;
            split2(make_float2(accS[tn][0], accS[tn][1]), hh, ll);
            sm->u.pp.Ph[rg16 + qr][cg * 32 + tn * 4 + qc] = hh;
            sm->u.pp.Pl[rg16 + qr][cg * 32 + tn * 4 + qc] = ll;
            split2(make_float2(accS[tn][2], accS[tn][3]), hh, ll);
            sm->u.pp.Ph[rg16 + qr + 8][cg * 32 + tn * 4 + qc] = hh;
            sm->u.pp.Pl[rg16 + qr + 8][cg * 32 + tn * 4 + qc] = ll;
        }
        __syncthreads();   // P + redsum ready

        const float cs0 = sm->redsum[rg16 + qr][0]     + sm->redsum[rg16 + qr][1];
        const float cs1 = sm->redsum[rg16 + qr + 8][0] + sm->redsum[rg16 + qr + 8][1];
        l0 = l0 * f0 + cs0; l1 = l1 * f1 + cs1; m0 = nm0; m1 = nm1;
        #pragma unroll
        for (int tn2 = 0; tn2 < 4; tn2++) {
            accO[tn2][0] *= f0; accO[tn2][1] *= f0;
            accO[tn2][2] *= f1; accO[tn2][3] *= f1;
        }

        // ---- accO += P @ V (warp: 16 rows x 32 out-cols, k over 128 j) ----
        {
            const unsigned (*Vhp)[68] = (const unsigned (*)[68])&sm->Vh[cg * 32];
            const unsigned (*Vlp)[68] = (const unsigned (*)[68])&sm->Vl[cg * 32];
            #pragma unroll
            for (int pb = 0; pb < 64; pb += 8)
                mma_k16_3<4, 68, 68>(accO, sm->u.pp.Ph, sm->u.pp.Pl, Vhp, Vlp, rg16, pb, qr, qc);
        }
        // next tile's first __syncthreads (after E load) protects P/V reuse
    }

    // ---- epilogue: normalize and write O[b, i, h*64+dd] ----
    const float inv0 = 1.f / l0, inv1 = 1.f / l1;
    #pragma unroll
    for (int tn2 = 0; tn2 < 4; tn2++) {
        const int r = i0 + rg16 + qr;
        const int col = h * HD + cg * 32 + tn2 * 8 + qc * 2;
        *(float2*)(g_O + (size_t)(b * SEQ + r) * DM + col) =
            make_float2(accO[tn2][0] * inv0, accO[tn2][1] * inv0);
        *(float2*)(g_O + (size_t)(b * SEQ + r + 8) * DM + col) =
            make_float2(accO[tn2][2] * inv1, accO[tn2][3] * inv1);
    }
}

// ---------------- launch ----------------
extern "C" void kernel_launch(void* const* d_in, const int* in_sizes, int n_in,
                              void* d_out, int out_size)
{
    const float* query = (const float*)d_in[0];
    const float* key   = (const float*)d_in[1];
    const float* value = (const float*)d_in[2];
    const float* WQ    = (const float*)d_in[3];
    const float* WK    = (const float*)d_in[4];
    const float* WV    = (const float*)d_in[5];
    const float* Er    = (const float*)d_in[6];
    const float* WM    = (const float*)d_in[7];
    float* out = (float*)d_out;

    static float *pQ = nullptr, *pK = nullptr, *pV = nullptr, *pO = nullptr;
    if (!pQ) {
        cudaGetSymbolAddress((void**)&pQ, g_Q);
        cudaGetSymbolAddress((void**)&pK, g_K);
        cudaGetSymbolAddress((void**)&pV, g_V);
        cudaGetSymbolAddress((void**)&pO, g_O);
        cudaFuncSetAttribute(flash_kernel, cudaFuncAttributeMaxDynamicSharedMemorySize,
                             (int)sizeof(FSmem));
    }

    const dim3 blk(256);
    const dim3 gProj(DM / 128, (BATCH * SEQ) / 128);   // (8, 32)

    bf_gemm_nn<<<gProj, blk>>>(query, WQ, pQ, BATCH * SEQ, DM, DM);
    bf_gemm_nn<<<gProj, blk>>>(key,   WK, pK, BATCH * SEQ, DM, DM);
    bf_gemm_nn<<<gProj, blk>>>(value, WV, pV, BATCH * SEQ, DM, DM);
    flash_kernel<<<dim3(SEQ / 128, BH), dim3(512), sizeof(FSmem)>>>(Er);
    bf_gemm_nn<<<gProj, blk>>>(pO, WM, out, BATCH * SEQ, DM, DM);
}

// round 8
// speedup vs baseline: 1.1176x; 1.1176x over previous
#include <cuda_runtime.h>
#include <cuda_bf16.h>

#define BATCH 4
#define SEQ   1024
#define DM    1024
#define HEADS 16
#define HD    64
#define BH    (BATCH*HEADS)

// ---------------- scratch (device globals; no allocs allowed) ----------------
__device__ float g_Q[BATCH*SEQ*DM];   // 16 MB
__device__ float g_K[BATCH*SEQ*DM];   // 16 MB
__device__ float g_V[BATCH*SEQ*DM];   // 16 MB
__device__ float g_O[BATCH*SEQ*DM];   // 16 MB

// ---------------- helpers ----------------
__device__ __forceinline__ void split2(float2 v, unsigned &h, unsigned &l) {
    __nv_bfloat162 bh = __float22bfloat162_rn(v);
    float2 back = __bfloat1622float2(bh);
    __nv_bfloat162 bl = __float22bfloat162_rn(make_float2(v.x - back.x, v.y - back.y));
    h = *(unsigned*)&bh;
    l = *(unsigned*)&bl;
}

__device__ __forceinline__ unsigned sptr(const void* p) {
    return (unsigned)__cvta_generic_to_shared(p);
}

__device__ __forceinline__ void ldsm4(unsigned r[4], unsigned a) {
    asm volatile("ldmatrix.sync.aligned.m8n8.x4.shared.b16 {%0,%1,%2,%3}, [%4];"
        : "=r"(r[0]), "=r"(r[1]), "=r"(r[2]), "=r"(r[3]) : "r"(a));
}

__device__ __forceinline__ void mma_bf16(float c[4], const unsigned a[4], const unsigned b[2]) {
    asm volatile(
        "mma.sync.aligned.m16n8k16.row.col.f32.bf16.bf16.f32 "
        "{%0,%1,%2,%3},{%4,%5,%6,%7},{%8,%9},{%0,%1,%2,%3};\n"
        : "+f"(c[0]), "+f"(c[1]), "+f"(c[2]), "+f"(c[3])
        : "r"(a[0]), "r"(a[1]), "r"(a[2]), "r"(a[3]), "r"(b[0]), "r"(b[1]));
}

// store 16 consecutive k floats (row-major) as 8 packed bf16 pairs (16B-aligned stores)
template<int P>
__device__ __forceinline__ void st_rm16(const float* src, unsigned (*H)[P], unsigned (*L)[P],
                                        int row, int p0) {
    unsigned h[8], l[8];
    #pragma unroll
    for (int i = 0; i < 4; i++) {
        const float4 x = *(const float4*)(src + 4 * i);
        split2(make_float2(x.x, x.y), h[2 * i], l[2 * i]);
        split2(make_float2(x.z, x.w), h[2 * i + 1], l[2 * i + 1]);
    }
    *(uint4*)&H[row][p0]     = make_uint4(h[0], h[1], h[2], h[3]);
    *(uint4*)&H[row][p0 + 4] = make_uint4(h[4], h[5], h[6], h[7]);
    *(uint4*)&L[row][p0]     = make_uint4(l[0], l[1], l[2], l[3]);
    *(uint4*)&L[row][p0 + 4] = make_uint4(l[4], l[5], l[6], l[7]);
}

template<int P>
__device__ __forceinline__ void st_rm16z(unsigned (*H)[P], unsigned (*L)[P], int row, int p0) {
    const uint4 z = make_uint4(0, 0, 0, 0);
    *(uint4*)&H[row][p0] = z; *(uint4*)&H[row][p0 + 4] = z;
    *(uint4*)&L[row][p0] = z; *(uint4*)&L[row][p0 + 4] = z;
}

// store a 2(k)x4(n) chunk from two k-rows into col-major B operand (scalar stores)
template<int P>
__device__ __forceinline__ void st_km2x4(float4 x0, float4 x1, unsigned (*H)[P],
                                         unsigned (*L)[P], int c, int kp) {
    unsigned h, l;
    split2(make_float2(x0.x, x1.x), h, l); H[c][kp] = h;     L[c][kp] = l;
    split2(make_float2(x0.y, x1.y), h, l); H[c + 1][kp] = h; L[c + 1][kp] = l;
    split2(make_float2(x0.z, x1.z), h, l); H[c + 2][kp] = h; L[c + 2][kp] = l;
    split2(make_float2(x0.w, x1.w), h, l); H[c + 3][kp] = h; L[c + 3][kp] = l;
}

// one k16 slab (pair base pb), TN n8-tiles (TN even), 3-term split MMA, ldmatrix feeds.
// A-frag: ldmatrix.x4 over rows arow+(lane&15), pairs pb + 4*(lane>>4).
// B-frag: ldmatrix.x4 = two consecutive n8 tiles; rows t2*16+(lane&7)+((lane&16)?8:0),
//         pairs pb + ((lane&8)?4:0).
template<int TN, int PA, int PB>
__device__ __forceinline__ void mma_k16_3(float (*acc)[4],
    const unsigned (*Ah)[PA], const unsigned (*Al)[PA],
    const unsigned (*Bh)[PB], const unsigned (*Bl)[PB],
    int arow, int pb, int lane)
{
    const int ar = arow + (lane & 15);
    const int ac = pb + ((lane >> 4) << 2);
    unsigned ah[4], al[4];
    ldsm4(ah, sptr(&Ah[ar][ac]));
    ldsm4(al, sptr(&Al[ar][ac]));
    const int br = (lane & 7) + ((lane & 16) >> 1);
    const int bc = pb + ((lane & 8) >> 1);
    #pragma unroll
    for (int t2 = 0; t2 < TN / 2; t2++) {
        unsigned bh[4], bl[4];
        ldsm4(bh, sptr(&Bh[t2 * 16 + br][bc]));
        ldsm4(bl, sptr(&Bl[t2 * 16 + br][bc]));
        mma_bf16(acc[2 * t2],     ah, &bh[0]);
        mma_bf16(acc[2 * t2],     al, &bh[0]);
        mma_bf16(acc[2 * t2],     ah, &bl[0]);
        mma_bf16(acc[2 * t2 + 1], ah, &bh[2]);
        mma_bf16(acc[2 * t2 + 1], al, &bh[2]);
        mma_bf16(acc[2 * t2 + 1], ah, &bl[2]);
    }
}

__device__ __forceinline__ const float* q_row(int b, int h, int i) {
    return g_Q + (size_t)(b * SEQ + h * HD + (i >> 4)) * DM + ((i & 15) << 6);
}
__device__ __forceinline__ const float* v_row(int b, int h, int j) {
    return g_V + (size_t)(b * SEQ + h * HD + (j >> 4)) * DM + ((j & 15) << 6);
}

// ==================== projection / merge GEMM ====================
__device__ __forceinline__ void mma32p(const unsigned (*Ah)[20], const unsigned (*Al)[20],
                                       const unsigned (*Bh)[20], const unsigned (*Bl)[20],
                                       float (*acc)[4][4], int warp_m, int warp_n, int lane) {
    #pragma unroll
    for (int s = 0; s < 2; s++) {
        const int pb = 8 * s;
        const int arl = lane & 15, acl = pb + ((lane >> 4) << 2);
        const int brl = (lane & 7) + ((lane & 16) >> 1), bcl = pb + ((lane & 8) >> 1);
        unsigned ah[4][4], al[4][4], bh[2][4], bl[2][4];
        #pragma unroll
        for (int tm = 0; tm < 4; tm++) {
            ldsm4(ah[tm], sptr(&Ah[warp_m + tm * 16 + arl][acl]));
            ldsm4(al[tm], sptr(&Al[warp_m + tm * 16 + arl][acl]));
        }
        #pragma unroll
        for (int t2 = 0; t2 < 2; t2++) {
            ldsm4(bh[t2], sptr(&Bh[warp_n + t2 * 16 + brl][bcl]));
            ldsm4(bl[t2], sptr(&Bl[warp_n + t2 * 16 + brl][bcl]));
        }
        #pragma unroll
        for (int tm = 0; tm < 4; tm++)
            #pragma unroll
            for (int t2 = 0; t2 < 2; t2++) {
                mma_bf16(acc[tm][2 * t2],     ah[tm], &bh[t2][0]);
                mma_bf16(acc[tm][2 * t2],     al[tm], &bh[t2][0]);
                mma_bf16(acc[tm][2 * t2],     ah[tm], &bl[t2][0]);
                mma_bf16(acc[tm][2 * t2 + 1], ah[tm], &bh[t2][2]);
                mma_bf16(acc[tm][2 * t2 + 1], al[tm], &bh[t2][2]);
                mma_bf16(acc[tm][2 * t2 + 1], ah[tm], &bl[t2][2]);
            }
    }
}

__global__ __launch_bounds__(256, 2) void bf_gemm_nn(const float* __restrict__ A,
                                                     const float* __restrict__ W,
                                                     float* __restrict__ C,
                                                     int M, int N, int K)
{
    __shared__ unsigned Ah[128][20], Al[128][20], Bh[128][20], Bl[128][20];
    const int tid = threadIdx.x, lane = tid & 31, w = tid >> 5;
    const int m0 = blockIdx.y << 7, n0 = blockIdx.x << 7;
    const int warp_m = (w >> 2) * 64, warp_n = (w & 3) * 32;
    const int am = tid >> 1, ako = (tid & 1) << 4;
    const int bkp = tid & 15, bcg = tid >> 4;
    float acc[4][4][4] = {};

    for (int k0 = 0; k0 < K; k0 += 32) {
        st_rm16<20>(A + (size_t)(m0 + am) * K + k0 + ako, Ah, Al, am, ako >> 1);
        #pragma unroll
        for (int rep = 0; rep < 2; rep++) {
            const int c = (bcg + 16 * rep) << 2;
            const float* p = W + (size_t)(k0 + 2 * bkp) * N + n0 + c;
            st_km2x4<20>(*(const float4*)p, *(const float4*)(p + N), Bh, Bl, c, bkp);
        }
        __syncthreads();
        mma32p(Ah, Al, Bh, Bl, acc, warp_m, warp_n, lane);
        __syncthreads();
    }
    const int qr = lane >> 2, qc = lane & 3;
    #pragma unroll
    for (int tm = 0; tm < 4; tm++)
        #pragma unroll
        for (int tn = 0; tn < 4; tn++) {
            const int r = m0 + warp_m + tm * 16 + qr;
            const int cN = n0 + warp_n + tn * 8 + qc * 2;
            *(float2*)(C + (size_t)r * N + cN)       = make_float2(acc[tm][tn][0], acc[tm][tn][1]);
            *(float2*)(C + (size_t)(r + 8) * N + cN) = make_float2(acc[tm][tn][2], acc[tm][tn][3]);
        }
}

// ==================== fused flash attention with relative bias (512 threads) ====================
struct FSmem {
    unsigned Qh[129][36], Ql[129][36];   // Q rows i0..i0+128 (129 for the +1 shift)
    unsigned Kh[128][36], Kl[128][36];   // K^T tile: [j][dd-pair]
    unsigned Eh[128][36], El[128][36];   // Er window: [e][dd-pair]
    unsigned Vh[64][68],  Vl[64][68];    // V tile: [dd][j-pair]
    union {
        float G[128][132];                        // rel-bias staging
        struct { unsigned Ph[128][68], Pl[128][68]; } pp;  // softmaxed P operand
    } u;
    float redmax[128][2];                 // cross-warp softmax staging
    float redsum[128][2];
};

__global__ __launch_bounds__(512, 1) void flash_kernel(const float* __restrict__ Er)
{
    extern __shared__ char raw[];
    FSmem* sm = (FSmem*)raw;
    const int tid = threadIdx.x, lane = tid & 31, w = tid >> 5;   // 16 warps
    const int qr = lane >> 2, qc = lane & 3;
    const int rg = w & 7, cg = w >> 3;        // row-group (16 rows), col-group (64 cols)
    const int rg16 = rg << 4;
    const int bh = blockIdx.y, b = bh >> 4, h = bh & 15;
    const int i0 = blockIdx.x << 7;

    // ---- load Q: 129 rows x 4 chunks of 16 floats ----
    #pragma unroll
    for (int it = 0; it < 2; it++) {
        const int idx = tid + it * 512;
        if (idx < 129 * 4) {
            const int r = idx >> 2, ch = idx & 3;
            if (i0 + r < SEQ) st_rm16<36>(q_row(b, h, i0 + r) + ch * 16, sm->Qh, sm->Ql, r, ch * 8);
            else              st_rm16z<36>(sm->Qh, sm->Ql, r, ch * 8);
        }
    }

    float accO[4][4] = {};                    // 16 rows x 32 cols per warp
    float m0 = -1e30f, m1 = -1e30f, l0 = 0.f, l1 = 0.f;
    const float* kbase = g_K + (size_t)(b * SEQ + h * HD) * DM;

    for (int jt = 0; jt < 8; jt++) {
        const int j0 = jt << 7;
        const int delta = j0 - i0;
        float accS[8][4] = {};               // 16 rows x 64 cols per warp

        // ---- relative-bias phases: G = Q(+shift) @ ErWindow^T, then diagonal gather ----
        #pragma unroll 1
        for (int band = 0; band < 2; band++) {       // 0 = lower (c<=i), 1 = upper (c>=i+2)
            if (band == 0 && delta > 0) continue;
            if (band == 1 && delta < 0) continue;
            const int ebase = (band == 0) ? (895 + delta) : (delta - 130);
            #pragma unroll 1
            for (int half = 0; half < 2; half++) {
                if (band == 1 && half == 0 && delta < 128) continue;
                {   // load Er window half: exactly 512 chunk-ops
                    const int r = tid >> 2, ch = tid & 3;
                    const int er = ebase + half * 128 + r;
                    if (er >= 0 && er < SEQ)
                        st_rm16<36>(Er + (size_t)er * HD + ch * 16, sm->Eh, sm->El, r, ch * 8);
                    else
                        st_rm16z<36>(sm->Eh, sm->El, r, ch * 8);
                }
                __syncthreads();   // E ready; also frees P/V from prior tile's MMA reads
                const int arow = rg16 + band;        // upper band uses q_{i+1}
                #pragma unroll 1
                for (int nh = 0; nh < 2; nh++) {     // two 32-col halves: gacc stays small
                    float gacc[4][4] = {};
                    const unsigned (*Ehp)[36] = (const unsigned (*)[36])&sm->Eh[cg * 64 + nh * 32];
                    const unsigned (*Elp)[36] = (const unsigned (*)[36])&sm->El[cg * 64 + nh * 32];
                    #pragma unroll
                    for (int pb = 0; pb < 32; pb += 8)
                        mma_k16_3<4, 36, 36>(gacc, sm->Qh, sm->Ql, Ehp, Elp, arow, pb, lane);
                    #pragma unroll
                    for (int tn = 0; tn < 4; tn++) {
                        const int r = rg16 + qr, c = cg * 64 + nh * 32 + tn * 8 + qc * 2;
                        *(float2*)&sm->u.G[r][c]     = make_float2(gacc[tn][0], gacc[tn][1]);
                        *(float2*)&sm->u.G[r + 8][c] = make_float2(gacc[tn][2], gacc[tn][3]);
                    }
                }
                __syncthreads();
                #pragma unroll
                for (int tn = 0; tn < 8; tn++)
                    #pragma unroll
                    for (int k = 0; k < 4; k++) {
                        const int r = rg16 + qr + ((k >> 1) << 3);
                        const int jc = cg * 64 + tn * 8 + qc * 2 + (k & 1);
                        const int diff = jc - r;
                        const bool cond = (band == 0) ? (diff <= -delta) : (diff >= 2 - delta);
                        const int mm = 128 + diff - half * 128;
                        if (cond && mm >= 0 && mm < 128) accS[tn][k] += sm->u.G[r][mm];
                    }
            }
        }

        // ---- load K^T and V tiles (512 threads, 2 iterations each) ----
        #pragma unroll
        for (int it = 0; it < 2; it++) {
            const int idx = tid + it * 512;
            const int kp = idx & 31, cgl = idx >> 5;
            const float* p = kbase + (size_t)(2 * kp) * DM + j0 + cgl * 4;
            st_km2x4<36>(*(const float4*)p, *(const float4*)(p + DM), sm->Kh, sm->Kl, cgl * 4, kp);
        }
        #pragma unroll
        for (int it = 0; it < 2; it++) {
            const int idx = tid + it * 512;
            const int jp = idx & 63, cgl = idx >> 6;
            const float4 x0 = *(const float4*)(v_row(b, h, j0 + 2 * jp)     + cgl * 4);
            const float4 x1 = *(const float4*)(v_row(b, h, j0 + 2 * jp + 1) + cgl * 4);
            st_km2x4<68>(x0, x1, sm->Vh, sm->Vl, cgl * 4, jp);
        }
        __syncthreads();   // K,V ready; all gathers done (G region free for P)

        // ---- q @ k^T accumulate on top of rel (warp: 16 rows x 64 cols) ----
        {
            const unsigned (*Khp)[36] = (const unsigned (*)[36])&sm->Kh[cg * 64];
            const unsigned (*Klp)[36] = (const unsigned (*)[36])&sm->Kl[cg * 64];
            #pragma unroll
            for (int pb = 0; pb < 32; pb += 8)
                mma_k16_3<8, 36, 36>(accS, sm->Qh, sm->Ql, Khp, Klp, rg16, pb, lane);
        }

        // ---- online softmax (logits = accS * 0.125), cross-warp over 2 col groups ----
        float tm0 = -1e30f, tm1 = -1e30f;
        #pragma unroll
        for (int tn = 0; tn < 8; tn++) {
            tm0 = fmaxf(tm0, fmaxf(accS[tn][0], accS[tn][1]));
            tm1 = fmaxf(tm1, fmaxf(accS[tn][2], accS[tn][3]));
        }
        tm0 = fmaxf(tm0, __shfl_xor_sync(0xffffffffu, tm0, 1));
        tm0 = fmaxf(tm0, __shfl_xor_sync(0xffffffffu, tm0, 2));
        tm1 = fmaxf(tm1, __shfl_xor_sync(0xffffffffu, tm1, 1));
        tm1 = fmaxf(tm1, __shfl_xor_sync(0xffffffffu, tm1, 2));
        tm0 *= 0.125f; tm1 *= 0.125f;
        if (qc == 0) {
            sm->redmax[rg16 + qr][cg]     = tm0;
            sm->redmax[rg16 + qr + 8][cg] = tm1;
        }
        __syncthreads();
        const float cm0 = fmaxf(sm->redmax[rg16 + qr][0],     sm->redmax[rg16 + qr][1]);
        const float cm1 = fmaxf(sm->redmax[rg16 + qr + 8][0], sm->redmax[rg16 + qr + 8][1]);
        const float nm0 = fmaxf(m0, cm0), nm1 = fmaxf(m1, cm1);
        const float f0 = __expf(m0 - nm0), f1 = __expf(m1 - nm1);
        float s0 = 0.f, s1 = 0.f;
        #pragma unroll
        for (int tn = 0; tn < 8; tn++) {
            accS[tn][0] = __expf(accS[tn][0] * 0.125f - nm0); s0 += accS[tn][0];
            accS[tn][1] = __expf(accS[tn][1] * 0.125f - nm0); s0 += accS[tn][1];
            accS[tn][2] = __expf(accS[tn][2] * 0.125f - nm1); s1 += accS[tn][2];
            accS[tn][3] = __expf(accS[tn][3] * 0.125f - nm1); s1 += accS[tn][3];
        }
        s0 += __shfl_xor_sync(0xffffffffu, s0, 1); s0 += __shfl_xor_sync(0xffffffffu, s0, 2);
        s1 += __shfl_xor_sync(0xffffffffu, s1, 1); s1 += __shfl_xor_sync(0xffffffffu, s1, 2);
        if (qc == 0) {
            sm->redsum[rg16 + qr][cg]     = s0;
            sm->redsum[rg16 + qr + 8][cg] = s1;
        }

        // ---- write split-bf16 P operand (overlap with sum staging; synced below) ----
        #pragma unroll
        for (int tn = 0; tn < 8; tn++) {
            unsigned hh, ll;
            split2(make_float2(accS[tn][0], accS[tn][1]), hh, ll);
            sm->u.pp.Ph[rg16 + qr][cg * 32 + tn * 4 + qc] = hh;
            sm->u.pp.Pl[rg16 + qr][cg * 32 + tn * 4 + qc] = ll;
            split2(make_float2(accS[tn][2], accS[tn][3]), hh, ll);
            sm->u.pp.Ph[rg16 + qr + 8][cg * 32 + tn * 4 + qc] = hh;
            sm->u.pp.Pl[rg16 + qr + 8][cg * 32 + tn * 4 + qc] = ll;
        }
        __syncthreads();   // P + redsum ready

        const float cs0 = sm->redsum[rg16 + qr][0]     + sm->redsum[rg16 + qr][1];
        const float cs1 = sm->redsum[rg16 + qr + 8][0] + sm->redsum[rg16 + qr + 8][1];
        l0 = l0 * f0 + cs0; l1 = l1 * f1 + cs1; m0 = nm0; m1 = nm1;
        #pragma unroll
        for (int tn2 = 0; tn2 < 4; tn2++) {
            accO[tn2][0] *= f0; accO[tn2][1] *= f0;
            accO[tn2][2] *= f1; accO[tn2][3] *= f1;
        }

        // ---- accO += P @ V (warp: 16 rows x 32 out-cols, k over 128 j) ----
        {
            const unsigned (*Vhp)[68] = (const unsigned (*)[68])&sm->Vh[cg * 32];
            const unsigned (*Vlp)[68] = (const unsigned (*)[68])&sm->Vl[cg * 32];
            #pragma unroll
            for (int pb = 0; pb < 64; pb += 8)
                mma_k16_3<4, 68, 68>(accO, sm->u.pp.Ph, sm->u.pp.Pl, Vhp, Vlp, rg16, pb, lane);
        }
        // next tile's first __syncthreads (after E load) protects P/V reuse
    }

    // ---- epilogue: normalize and write O[b, i, h*64+dd] ----
    const float inv0 = 1.f / l0, inv1 = 1.f / l1;
    #pragma unroll
    for (int tn2 = 0; tn2 < 4; tn2++) {
        const int r = i0 + rg16 + qr;
        const int col = h * HD + cg * 32 + tn2 * 8 + qc * 2;
        *(float2*)(g_O + (size_t)(b * SEQ + r) * DM + col) =
            make_float2(accO[tn2][0] * inv0, accO[tn2][1] * inv0);
        *(float2*)(g_O + (size_t)(b * SEQ + r + 8) * DM + col) =
            make_float2(accO[tn2][2] * inv1, accO[tn2][3] * inv1);
    }
}

// ---------------- launch ----------------
extern "C" void kernel_launch(void* const* d_in, const int* in_sizes, int n_in,
                              void* d_out, int out_size)
{
    const float* query = (const float*)d_in[0];
    const float* key   = (const float*)d_in[1];
    const float* value = (const float*)d_in[2];
    const float* WQ    = (const float*)d_in[3];
    const float* WK    = (const float*)d_in[4];
    const float* WV    = (const float*)d_in[5];
    const float* Er    = (const float*)d_in[6];
    const float* WM    = (const float*)d_in[7];
    float* out = (float*)d_out;

    static float *pQ = nullptr, *pK = nullptr, *pV = nullptr, *pO = nullptr;
    if (!pQ) {
        cudaGetSymbolAddress((void**)&pQ, g_Q);
        cudaGetSymbolAddress((void**)&pK, g_K);
        cudaGetSymbolAddress((void**)&pV, g_V);
        cudaGetSymbolAddress((void**)&pO, g_O);
        cudaFuncSetAttribute(flash_kernel, cudaFuncAttributeMaxDynamicSharedMemorySize,
                             (int)sizeof(FSmem));
    }

    const dim3 blk(256);
    const dim3 gProj(DM / 128, (BATCH * SEQ) / 128);   // (8, 32)

    bf_gemm_nn<<<gProj, blk>>>(query, WQ, pQ, BATCH * SEQ, DM, DM);
    bf_gemm_nn<<<gProj, blk>>>(key,   WK, pK, BATCH * SEQ, DM, DM);
    bf_gemm_nn<<<gProj, blk>>>(value, WV, pV, BATCH * SEQ, DM, DM);
    flash_kernel<<<dim3(SEQ / 128, BH), dim3(512), sizeof(FSmem)>>>(Er);
    bf_gemm_nn<<<gProj, blk>>>(pO, WM, out, BATCH * SEQ, DM, DM);
}

// round 9
// speedup vs baseline: 1.2351x; 1.1052x over previous
#include <cuda_runtime.h>
#include <cuda_bf16.h>

#define BATCH 4
#define SEQ   1024
#define DM    1024
#define HEADS 16
#define HD    64
#define BH    (BATCH*HEADS)

// ---------------- scratch (device globals; no allocs allowed) ----------------
__device__ float g_Q[BATCH*SEQ*DM];   // 16 MB
__device__ float g_K[BATCH*SEQ*DM];   // 16 MB
__device__ float g_V[BATCH*SEQ*DM];   // 16 MB
__device__ float g_O[BATCH*SEQ*DM];   // 16 MB

// ---------------- helpers ----------------
__device__ __forceinline__ void split2(float2 v, unsigned &h, unsigned &l) {
    __nv_bfloat162 bh = __float22bfloat162_rn(v);
    float2 back = __bfloat1622float2(bh);
    __nv_bfloat162 bl = __float22bfloat162_rn(make_float2(v.x - back.x, v.y - back.y));
    h = *(unsigned*)&bh;
    l = *(unsigned*)&bl;
}

__device__ __forceinline__ unsigned pack_hi2(float2 v) {
    __nv_bfloat162 bh = __float22bfloat162_rn(v);
    return *(unsigned*)&bh;
}

__device__ __forceinline__ unsigned sptr(const void* p) {
    return (unsigned)__cvta_generic_to_shared(p);
}

__device__ __forceinline__ void ldsm4(unsigned r[4], unsigned a) {
    asm volatile("ldmatrix.sync.aligned.m8n8.x4.shared.b16 {%0,%1,%2,%3}, [%4];"
        : "=r"(r[0]), "=r"(r[1]), "=r"(r[2]), "=r"(r[3]) : "r"(a));
}

__device__ __forceinline__ void mma_bf16(float c[4], const unsigned a[4], const unsigned b[2]) {
    asm volatile(
        "mma.sync.aligned.m16n8k16.row.col.f32.bf16.bf16.f32 "
        "{%0,%1,%2,%3},{%4,%5,%6,%7},{%8,%9},{%0,%1,%2,%3};\n"
        : "+f"(c[0]), "+f"(c[1]), "+f"(c[2]), "+f"(c[3])
        : "r"(a[0]), "r"(a[1]), "r"(a[2]), "r"(a[3]), "r"(b[0]), "r"(b[1]));
}

// store 16 consecutive k floats (row-major) as 8 packed bf16 pairs (16B-aligned stores)
template<int P>
__device__ __forceinline__ void st_rm16(const float* src, unsigned (*H)[P], unsigned (*L)[P],
                                        int row, int p0) {
    unsigned h[8], l[8];
    #pragma unroll
    for (int i = 0; i < 4; i++) {
        const float4 x = *(const float4*)(src + 4 * i);
        split2(make_float2(x.x, x.y), h[2 * i], l[2 * i]);
        split2(make_float2(x.z, x.w), h[2 * i + 1], l[2 * i + 1]);
    }
    *(uint4*)&H[row][p0]     = make_uint4(h[0], h[1], h[2], h[3]);
    *(uint4*)&H[row][p0 + 4] = make_uint4(h[4], h[5], h[6], h[7]);
    *(uint4*)&L[row][p0]     = make_uint4(l[0], l[1], l[2], l[3]);
    *(uint4*)&L[row][p0 + 4] = make_uint4(l[4], l[5], l[6], l[7]);
}

template<int P>
__device__ __forceinline__ void st_rm16z(unsigned (*H)[P], unsigned (*L)[P], int row, int p0) {
    const uint4 z = make_uint4(0, 0, 0, 0);
    *(uint4*)&H[row][p0] = z; *(uint4*)&H[row][p0 + 4] = z;
    *(uint4*)&L[row][p0] = z; *(uint4*)&L[row][p0 + 4] = z;
}

// hi-only variant (bias operand): 16 floats -> 8 bf16 pairs, H only
template<int P>
__device__ __forceinline__ void st_rm16h(const float* src, unsigned (*H)[P], int row, int p0) {
    unsigned h[8];
    #pragma unroll
    for (int i = 0; i < 4; i++) {
        const float4 x = *(const float4*)(src + 4 * i);
        h[2 * i]     = pack_hi2(make_float2(x.x, x.y));
        h[2 * i + 1] = pack_hi2(make_float2(x.z, x.w));
    }
    *(uint4*)&H[row][p0]     = make_uint4(h[0], h[1], h[2], h[3]);
    *(uint4*)&H[row][p0 + 4] = make_uint4(h[4], h[5], h[6], h[7]);
}

template<int P>
__device__ __forceinline__ void st_rm16hz(unsigned (*H)[P], int row, int p0) {
    const uint4 z = make_uint4(0, 0, 0, 0);
    *(uint4*)&H[row][p0] = z; *(uint4*)&H[row][p0 + 4] = z;
}

// store a 2(k)x4(n) chunk from two k-rows into col-major B operand (scalar stores)
template<int P>
__device__ __forceinline__ void st_km2x4(float4 x0, float4 x1, unsigned (*H)[P],
                                         unsigned (*L)[P], int c, int kp) {
    unsigned h, l;
    split2(make_float2(x0.x, x1.x), h, l); H[c][kp] = h;     L[c][kp] = l;
    split2(make_float2(x0.y, x1.y), h, l); H[c + 1][kp] = h; L[c + 1][kp] = l;
    split2(make_float2(x0.z, x1.z), h, l); H[c + 2][kp] = h; L[c + 2][kp] = l;
    split2(make_float2(x0.w, x1.w), h, l); H[c + 3][kp] = h; L[c + 3][kp] = l;
}

// one k16 slab (pair base pb), TN n8-tiles (TN even), 3-term split MMA, ldmatrix feeds.
template<int TN, int PA, int PB>
__device__ __forceinline__ void mma_k16_3(float (*acc)[4],
    const unsigned (*Ah)[PA], const unsigned (*Al)[PA],
    const unsigned (*Bh)[PB], const unsigned (*Bl)[PB],
    int arow, int pb, int lane)
{
    const int ar = arow + (lane & 15);
    const int ac = pb + ((lane >> 4) << 2);
    unsigned ah[4], al[4];
    ldsm4(ah, sptr(&Ah[ar][ac]));
    ldsm4(al, sptr(&Al[ar][ac]));
    const int br = (lane & 7) + ((lane & 16) >> 1);
    const int bc = pb + ((lane & 8) >> 1);
    #pragma unroll
    for (int t2 = 0; t2 < TN / 2; t2++) {
        unsigned bh[4], bl[4];
        ldsm4(bh, sptr(&Bh[t2 * 16 + br][bc]));
        ldsm4(bl, sptr(&Bl[t2 * 16 + br][bc]));
        mma_bf16(acc[2 * t2],     ah, &bh[0]);
        mma_bf16(acc[2 * t2],     al, &bh[0]);
        mma_bf16(acc[2 * t2],     ah, &bl[0]);
        mma_bf16(acc[2 * t2 + 1], ah, &bh[2]);
        mma_bf16(acc[2 * t2 + 1], al, &bh[2]);
        mma_bf16(acc[2 * t2 + 1], ah, &bl[2]);
    }
}

// hi-only slab (bias GEMM): 1 MMA per n8 tile
template<int TN, int PA, int PB>
__device__ __forceinline__ void mma_k16_1(float (*acc)[4],
    const unsigned (*Ah)[PA], const unsigned (*Bh)[PB],
    int arow, int pb, int lane)
{
    const int ar = arow + (lane & 15);
    const int ac = pb + ((lane >> 4) << 2);
    unsigned ah[4];
    ldsm4(ah, sptr(&Ah[ar][ac]));
    const int br = (lane & 7) + ((lane & 16) >> 1);
    const int bc = pb + ((lane & 8) >> 1);
    #pragma unroll
    for (int t2 = 0; t2 < TN / 2; t2++) {
        unsigned bh[4];
        ldsm4(bh, sptr(&Bh[t2 * 16 + br][bc]));
        mma_bf16(acc[2 * t2],     ah, &bh[0]);
        mma_bf16(acc[2 * t2 + 1], ah, &bh[2]);
    }
}

__device__ __forceinline__ const float* q_row(int b, int h, int i) {
    return g_Q + (size_t)(b * SEQ + h * HD + (i >> 4)) * DM + ((i & 15) << 6);
}
__device__ __forceinline__ const float* v_row(int b, int h, int j) {
    return g_V + (size_t)(b * SEQ + h * HD + (j >> 4)) * DM + ((j & 15) << 6);
}

// ==================== projection / merge GEMM ====================
__device__ __forceinline__ void mma32p(const unsigned (*Ah)[20], const unsigned (*Al)[20],
                                       const unsigned (*Bh)[20], const unsigned (*Bl)[20],
                                       float (*acc)[4][4], int warp_m, int warp_n, int lane) {
    #pragma unroll
    for (int s = 0; s < 2; s++) {
        const int pb = 8 * s;
        const int arl = lane & 15, acl = pb + ((lane >> 4) << 2);
        const int brl = (lane & 7) + ((lane & 16) >> 1), bcl = pb + ((lane & 8) >> 1);
        unsigned ah[4][4], al[4][4], bh[2][4], bl[2][4];
        #pragma unroll
        for (int tm = 0; tm < 4; tm++) {
            ldsm4(ah[tm], sptr(&Ah[warp_m + tm * 16 + arl][acl]));
            ldsm4(al[tm], sptr(&Al[warp_m + tm * 16 + arl][acl]));
        }
        #pragma unroll
        for (int t2 = 0; t2 < 2; t2++) {
            ldsm4(bh[t2], sptr(&Bh[warp_n + t2 * 16 + brl][bcl]));
            ldsm4(bl[t2], sptr(&Bl[warp_n + t2 * 16 + brl][bcl]));
        }
        #pragma unroll
        for (int tm = 0; tm < 4; tm++)
            #pragma unroll
            for (int t2 = 0; t2 < 2; t2++) {
                mma_bf16(acc[tm][2 * t2],     ah[tm], &bh[t2][0]);
                mma_bf16(acc[tm][2 * t2],     al[tm], &bh[t2][0]);
                mma_bf16(acc[tm][2 * t2],     ah[tm], &bl[t2][0]);
                mma_bf16(acc[tm][2 * t2 + 1], ah[tm], &bh[t2][2]);
                mma_bf16(acc[tm][2 * t2 + 1], al[tm], &bh[t2][2]);
                mma_bf16(acc[tm][2 * t2 + 1], ah[tm], &bl[t2][2]);
            }
    }
}

__global__ __launch_bounds__(256, 2) void bf_gemm_nn(const float* __restrict__ A,
                                                     const float* __restrict__ W,
                                                     float* __restrict__ C,
                                                     int M, int N, int K)
{
    __shared__ unsigned Ah[128][20], Al[128][20], Bh[128][20], Bl[128][20];
    const int tid = threadIdx.x, lane = tid & 31, w = tid >> 5;
    const int m0 = blockIdx.y << 7, n0 = blockIdx.x << 7;
    const int warp_m = (w >> 2) * 64, warp_n = (w & 3) * 32;
    const int am = tid >> 1, ako = (tid & 1) << 4;
    const int bkp = tid & 15, bcg = tid >> 4;
    float acc[4][4][4] = {};

    for (int k0 = 0; k0 < K; k0 += 32) {
        st_rm16<20>(A + (size_t)(m0 + am) * K + k0 + ako, Ah, Al, am, ako >> 1);
        #pragma unroll
        for (int rep = 0; rep < 2; rep++) {
            const int c = (bcg + 16 * rep) << 2;
            const float* p = W + (size_t)(k0 + 2 * bkp) * N + n0 + c;
            st_km2x4<20>(*(const float4*)p, *(const float4*)(p + N), Bh, Bl, c, bkp);
        }
        __syncthreads();
        mma32p(Ah, Al, Bh, Bl, acc, warp_m, warp_n, lane);
        __syncthreads();
    }
    const int qr = lane >> 2, qc = lane & 3;
    #pragma unroll
    for (int tm = 0; tm < 4; tm++)
        #pragma unroll
        for (int tn = 0; tn < 4; tn++) {
            const int r = m0 + warp_m + tm * 16 + qr;
            const int cN = n0 + warp_n + tn * 8 + qc * 2;
            *(float2*)(C + (size_t)r * N + cN)       = make_float2(acc[tm][tn][0], acc[tm][tn][1]);
            *(float2*)(C + (size_t)(r + 8) * N + cN) = make_float2(acc[tm][tn][2], acc[tm][tn][3]);
        }
}

// ==================== fused flash attention with relative bias (512 threads) ====================
struct FSmem {
    unsigned Qh[129][36], Ql[129][36];   // Q rows i0..i0+128 (129 for the +1 shift)
    unsigned Kh[128][36], Kl[128][36];   // K^T tile: [j][dd-pair]
    unsigned Eh[128][36];                // Er window (hi-only; bias is bf16-precision)
    unsigned Vh[64][68],  Vl[64][68];    // V tile: [dd][j-pair]
    union {
        float G[128][132];                        // rel-bias staging
        struct { unsigned Ph[128][68], Pl[128][68]; } pp;  // softmaxed P operand
    } u;
    float redmax[128][2];                 // cross-warp softmax staging
    float redsum[128][2];
};

__global__ __launch_bounds__(512, 1) void flash_kernel(const float* __restrict__ Er)
{
    extern __shared__ char raw[];
    FSmem* sm = (FSmem*)raw;
    const int tid = threadIdx.x, lane = tid & 31, w = tid >> 5;   // 16 warps
    const int qr = lane >> 2, qc = lane & 3;
    const int rg = w & 7, cg = w >> 3;        // row-group (16 rows), col-group (64 cols)
    const int rg16 = rg << 4;
    const int bh = blockIdx.y, b = bh >> 4, h = bh & 15;
    const int i0 = blockIdx.x << 7;

    // ---- load Q: 129 rows x 4 chunks of 16 floats ----
    #pragma unroll
    for (int it = 0; it < 2; it++) {
        const int idx = tid + it * 512;
        if (idx < 129 * 4) {
            const int r = idx >> 2, ch = idx & 3;
            if (i0 + r < SEQ) st_rm16<36>(q_row(b, h, i0 + r) + ch * 16, sm->Qh, sm->Ql, r, ch * 8);
            else              st_rm16z<36>(sm->Qh, sm->Ql, r, ch * 8);
        }
    }

    float accO[4][4] = {};                    // 16 rows x 32 cols per warp
    float m0 = -1e30f, m1 = -1e30f, l0 = 0.f, l1 = 0.f;
    const float* kbase = g_K + (size_t)(b * SEQ + h * HD) * DM;

    for (int jt = 0; jt < 8; jt++) {
        const int j0 = jt << 7;
        const int delta = j0 - i0;
        float accS[8][4] = {};               // 16 rows x 64 cols per warp

        // ---- relative-bias phases: G = Q(+shift) @ ErWindow^T (hi-only), diagonal gather ----
        #pragma unroll 1
        for (int band = 0; band < 2; band++) {       // 0 = lower (c<=i), 1 = upper (c>=i+2)
            if (band == 0 && delta > 0) continue;
            if (band == 1 && delta < 0) continue;
            const int ebase = (band == 0) ? (895 + delta) : (delta - 130);
            #pragma unroll 1
            for (int half = 0; half < 2; half++) {
                if (band == 1 && half == 0 && delta < 128) continue;
                {   // load Er window half (hi-only): exactly 512 chunk-ops
                    const int r = tid >> 2, ch = tid & 3;
                    const int er = ebase + half * 128 + r;
                    if (er >= 0 && er < SEQ)
                        st_rm16h<36>(Er + (size_t)er * HD + ch * 16, sm->Eh, r, ch * 8);
                    else
                        st_rm16hz<36>(sm->Eh, r, ch * 8);
                }
                __syncthreads();   // E ready; also frees P/V from prior tile's MMA reads
                const int arow = rg16 + band;        // upper band uses q_{i+1}
                #pragma unroll 1
                for (int nh = 0; nh < 2; nh++) {     // two 32-col halves
                    float gacc[4][4] = {};
                    const unsigned (*Ehp)[36] = (const unsigned (*)[36])&sm->Eh[cg * 64 + nh * 32];
                    #pragma unroll
                    for (int pb = 0; pb < 32; pb += 8)
                        mma_k16_1<4, 36, 36>(gacc, sm->Qh, Ehp, arow, pb, lane);
                    #pragma unroll
                    for (int tn = 0; tn < 4; tn++) {
                        const int r = rg16 + qr, c = cg * 64 + nh * 32 + tn * 8 + qc * 2;
                        *(float2*)&sm->u.G[r][c]     = make_float2(gacc[tn][0], gacc[tn][1]);
                        *(float2*)&sm->u.G[r + 8][c] = make_float2(gacc[tn][2], gacc[tn][3]);
                    }
                }
                __syncthreads();
                #pragma unroll
                for (int tn = 0; tn < 8; tn++)
                    #pragma unroll
                    for (int k = 0; k < 4; k++) {
                        const int r = rg16 + qr + ((k >> 1) << 3);
                        const int jc = cg * 64 + tn * 8 + qc * 2 + (k & 1);
                        const int diff = jc - r;
                        const bool cond = (band == 0) ? (diff <= -delta) : (diff >= 2 - delta);
                        const int mm = 128 + diff - half * 128;
                        if (cond && mm >= 0 && mm < 128) accS[tn][k] += sm->u.G[r][mm];
                    }
            }
        }

        // ---- load K^T and V tiles (512 threads, 2 iterations each) ----
        #pragma unroll
        for (int it = 0; it < 2; it++) {
            const int idx = tid + it * 512;
            const int kp = idx & 31, cgl = idx >> 5;
            const float* p = kbase + (size_t)(2 * kp) * DM + j0 + cgl * 4;
            st_km2x4<36>(*(const float4*)p, *(const float4*)(p + DM), sm->Kh, sm->Kl, cgl * 4, kp);
        }
        #pragma unroll
        for (int it = 0; it < 2; it++) {
            const int idx = tid + it * 512;
            const int jp = idx & 63, cgl = idx >> 6;
            const float4 x0 = *(const float4*)(v_row(b, h, j0 + 2 * jp)     + cgl * 4);
            const float4 x1 = *(const float4*)(v_row(b, h, j0 + 2 * jp + 1) + cgl * 4);
            st_km2x4<68>(x0, x1, sm->Vh, sm->Vl, cgl * 4, jp);
        }
        __syncthreads();   // K,V ready; all gathers done (G region free for P)

        // ---- q @ k^T accumulate on top of rel (warp: 16 rows x 64 cols) ----
        {
            const unsigned (*Khp)[36] = (const unsigned (*)[36])&sm->Kh[cg * 64];
            const unsigned (*Klp)[36] = (const unsigned (*)[36])&sm->Kl[cg * 64];
            #pragma unroll
            for (int pb = 0; pb < 32; pb += 8)
                mma_k16_3<8, 36, 36>(accS, sm->Qh, sm->Ql, Khp, Klp, rg16, pb, lane);
        }

        // ---- online softmax (logits = accS * 0.125), cross-warp over 2 col groups ----
        float tm0 = -1e30f, tm1 = -1e30f;
        #pragma unroll
        for (int tn = 0; tn < 8; tn++) {
            tm0 = fmaxf(tm0, fmaxf(accS[tn][0], accS[tn][1]));
            tm1 = fmaxf(tm1, fmaxf(accS[tn][2], accS[tn][3]));
        }
        tm0 = fmaxf(tm0, __shfl_xor_sync(0xffffffffu, tm0, 1));
        tm0 = fmaxf(tm0, __shfl_xor_sync(0xffffffffu, tm0, 2));
        tm1 = fmaxf(tm1, __shfl_xor_sync(0xffffffffu, tm1, 1));
        tm1 = fmaxf(tm1, __shfl_xor_sync(0xffffffffu, tm1, 2));
        tm0 *= 0.125f; tm1 *= 0.125f;
        if (qc == 0) {
            sm->redmax[rg16 + qr][cg]     = tm0;
            sm->redmax[rg16 + qr + 8][cg] = tm1;
        }
        __syncthreads();
        const float cm0 = fmaxf(sm->redmax[rg16 + qr][0],     sm->redmax[rg16 + qr][1]);
        const float cm1 = fmaxf(sm->redmax[rg16 + qr + 8][0], sm->redmax[rg16 + qr + 8][1]);
        const float nm0 = fmaxf(m0, cm0), nm1 = fmaxf(m1, cm1);
        const float f0 = __expf(m0 - nm0), f1 = __expf(m1 - nm1);
        float s0 = 0.f, s1 = 0.f;
        #pragma unroll
        for (int tn = 0; tn < 8; tn++) {
            accS[tn][0] = __expf(accS[tn][0] * 0.125f - nm0); s0 += accS[tn][0];
            accS[tn][1] = __expf(accS[tn][1] * 0.125f - nm0); s0 += accS[tn][1];
            accS[tn][2] = __expf(accS[tn][2] * 0.125f - nm1); s1 += accS[tn][2];
            accS[tn][3] = __expf(accS[tn][3] * 0.125f - nm1); s1 += accS[tn][3];
        }
        s0 += __shfl_xor_sync(0xffffffffu, s0, 1); s0 += __shfl_xor_sync(0xffffffffu, s0, 2);
        s1 += __shfl_xor_sync(0xffffffffu, s1, 1); s1 += __shfl_xor_sync(0xffffffffu, s1, 2);
        if (qc == 0) {
            sm->redsum[rg16 + qr][cg]     = s0;
            sm->redsum[rg16 + qr + 8][cg] = s1;
        }

        // ---- write split-bf16 P operand (overlap with sum staging; synced below) ----
        #pragma unroll
        for (int tn = 0; tn < 8; tn++) {
            unsigned hh, ll;
            split2(make_float2(accS[tn][0], accS[tn][1]), hh, ll);
            sm->u.pp.Ph[rg16 + qr][cg * 32 + tn * 4 + qc] = hh;
            sm->u.pp.Pl[rg16 + qr][cg * 32 + tn * 4 + qc] = ll;
            split2(make_float2(accS[tn][2], accS[tn][3]), hh, ll);
            sm->u.pp.Ph[rg16 + qr + 8][cg * 32 + tn * 4 + qc] = hh;
            sm->u.pp.Pl[rg16 + qr + 8][cg * 32 + tn * 4 + qc] = ll;
        }
        __syncthreads();   // P + redsum ready

        const float cs0 = sm->redsum[rg16 + qr][0]     + sm->redsum[rg16 + qr][1];
        const float cs1 = sm->redsum[rg16 + qr + 8][0] + sm->redsum[rg16 + qr + 8][1];
        l0 = l0 * f0 + cs0; l1 = l1 * f1 + cs1; m0 = nm0; m1 = nm1;
        #pragma unroll
        for (int tn2 = 0; tn2 < 4; tn2++) {
            accO[tn2][0] *= f0; accO[tn2][1] *= f0;
            accO[tn2][2] *= f1; accO[tn2][3] *= f1;
        }

        // ---- accO += P @ V (warp: 16 rows x 32 out-cols, k over 128 j) ----
        {
            const unsigned (*Vhp)[68] = (const unsigned (*)[68])&sm->Vh[cg * 32];
            const unsigned (*Vlp)[68] = (const unsigned (*)[68])&sm->Vl[cg * 32];
            #pragma unroll
            for (int pb = 0; pb < 64; pb += 8)
                mma_k16_3<4, 68, 68>(accO, sm->u.pp.Ph, sm->u.pp.Pl, Vhp, Vlp, rg16, pb, lane);
        }
        // next tile's first __syncthreads (after E load) protects P/V reuse
    }

    // ---- epilogue: normalize and write O[b, i, h*64+dd] ----
    const float inv0 = 1.f / l0, inv1 = 1.f / l1;
    #pragma unroll
    for (int tn2 = 0; tn2 < 4; tn2++) {
        const int r = i0 + rg16 + qr;
        const int col = h * HD + cg * 32 + tn2 * 8 + qc * 2;
        *(float2*)(g_O + (size_t)(b * SEQ + r) * DM + col) =
            make_float2(accO[tn2][0] * inv0, accO[tn2][1] * inv0);
        *(float2*)(g_O + (size_t)(b * SEQ + r + 8) * DM + col) =
            make_float2(accO[tn2][2] * inv1, accO[tn2][3] * inv1);
    }
}

// ---------------- launch ----------------
extern "C" void kernel_launch(void* const* d_in, const int* in_sizes, int n_in,
                              void* d_out, int out_size)
{
    const float* query = (const float*)d_in[0];
    const float* key   = (const float*)d_in[1];
    const float* value = (const float*)d_in[2];
    const float* WQ    = (const float*)d_in[3];
    const float* WK    = (const float*)d_in[4];
    const float* WV    = (const float*)d_in[5];
    const float* Er    = (const float*)d_in[6];
    const float* WM    = (const float*)d_in[7];
    float* out = (float*)d_out;

    static float *pQ = nullptr, *pK = nullptr, *pV = nullptr, *pO = nullptr;
    if (!pQ) {
        cudaGetSymbolAddress((void**)&pQ, g_Q);
        cudaGetSymbolAddress((void**)&pK, g_K);
        cudaGetSymbolAddress((void**)&pV, g_V);
        cudaGetSymbolAddress((void**)&pO, g_O);
        cudaFuncSetAttribute(flash_kernel, cudaFuncAttributeMaxDynamicSharedMemorySize,
                             (int)sizeof(FSmem));
    }

    const dim3 blk(256);
    const dim3 gProj(DM / 128, (BATCH * SEQ) / 128);   // (8, 32)

    bf_gemm_nn<<<gProj, blk>>>(query, WQ, pQ, BATCH * SEQ, DM, DM);
    bf_gemm_nn<<<gProj, blk>>>(key,   WK, pK, BATCH * SEQ, DM, DM);
    bf_gemm_nn<<<gProj, blk>>>(value, WV, pV, BATCH * SEQ, DM, DM);
    flash_kernel<<<dim3(SEQ / 128, BH), dim3(512), sizeof(FSmem)>>>(Er);
    bf_gemm_nn<<<gProj, blk>>>(pO, WM, out, BATCH * SEQ, DM, DM);
}

// round 11
// speedup vs baseline: 1.3389x; 1.0840x over previous
#include <cuda_runtime.h>
#include <cuda_bf16.h>

#define BATCH 4
#define SEQ   1024
#define DM    1024
#define HEADS 16
#define HD    64
#define BH    (BATCH*HEADS)
#define MTOK  (BATCH*SEQ)          // 4096
#define KP    (DM/2)               // 512 packed pairs per row

// ---------------- scratch (device globals; no allocs allowed) ----------------
__device__ unsigned g_inh[3u*MTOK*KP], g_inl[3u*MTOK*KP];   // packed inputs (q,k,v)
__device__ unsigned g_wh[4u*DM*KP],   g_wl[4u*DM*KP];       // packed weights (col-major)
__device__ unsigned g_Qh[MTOK*KP],    g_Ql[MTOK*KP];        // packed Q projection
__device__ float    g_K[MTOK*DM],     g_V[MTOK*DM];         // fp32 K,V projections
__device__ unsigned g_Oh[MTOK*KP],    g_Ol[MTOK*KP];        // packed attention out
__device__ unsigned g_Eh[SEQ*(HD/2)], g_El[SEQ*(HD/2)];     // packed Er (hi used)

// ---------------- helpers ----------------
__device__ __forceinline__ void split2(float2 v, unsigned &h, unsigned &l) {
    __nv_bfloat162 bh = __float22bfloat162_rn(v);
    float2 back = __bfloat1622float2(bh);
    __nv_bfloat162 bl = __float22bfloat162_rn(make_float2(v.x - back.x, v.y - back.y));
    h = *(unsigned*)&bh;
    l = *(unsigned*)&bl;
}

__device__ __forceinline__ unsigned sptr(const void* p) {
    return (unsigned)__cvta_generic_to_shared(p);
}

__device__ __forceinline__ void cpa16(unsigned dst, const void* src) {
    asm volatile("cp.async.cg.shared.global [%0], [%1], 16;" :: "r"(dst), "l"(src) : "memory");
}

__device__ __forceinline__ void ldsm4(unsigned r[4], unsigned a) {
    asm volatile("ldmatrix.sync.aligned.m8n8.x4.shared.b16 {%0,%1,%2,%3}, [%4];"
        : "=r"(r[0]), "=r"(r[1]), "=r"(r[2]), "=r"(r[3]) : "r"(a));
}

__device__ __forceinline__ void mma_bf16(float c[4], const unsigned a[4], const unsigned b[2]) {
    asm volatile(
        "mma.sync.aligned.m16n8k16.row.col.f32.bf16.bf16.f32 "
        "{%0,%1,%2,%3},{%4,%5,%6,%7},{%8,%9},{%0,%1,%2,%3};\n"
        : "+f"(c[0]), "+f"(c[1]), "+f"(c[2]), "+f"(c[3])
        : "r"(a[0]), "r"(a[1]), "r"(a[2]), "r"(a[3]), "r"(b[0]), "r"(b[1]));
}

// store a 2(k)x4(n) chunk from two k-rows into col-major B operand (scalar stores)
template<int P>
__device__ __forceinline__ void st_km2x4(float4 x0, float4 x1, unsigned (*H)[P],
                                         unsigned (*L)[P], int c, int kp) {
    unsigned h, l;
    split2(make_float2(x0.x, x1.x), h, l); H[c][kp] = h;     L[c][kp] = l;
    split2(make_float2(x0.y, x1.y), h, l); H[c + 1][kp] = h; L[c + 1][kp] = l;
    split2(make_float2(x0.z, x1.z), h, l); H[c + 2][kp] = h; L[c + 2][kp] = l;
    split2(make_float2(x0.w, x1.w), h, l); H[c + 3][kp] = h; L[c + 3][kp] = l;
}

// one k16 slab (pair base pb), TN n8-tiles (TN even), 3-term split MMA, ldmatrix feeds.
template<int TN, int PA, int PB>
__device__ __forceinline__ void mma_k16_3(float (*acc)[4],
    const unsigned (*Ah)[PA], const unsigned (*Al)[PA],
    const unsigned (*Bh)[PB], const unsigned (*Bl)[PB],
    int arow, int pb, int lane)
{
    const int ar = arow + (lane & 15);
    const int ac = pb + ((lane >> 4) << 2);
    unsigned ah[4], al[4];
    ldsm4(ah, sptr(&Ah[ar][ac]));
    ldsm4(al, sptr(&Al[ar][ac]));
    const int br = (lane & 7) + ((lane & 16) >> 1);
    const int bc = pb + ((lane & 8) >> 1);
    #pragma unroll
    for (int t2 = 0; t2 < TN / 2; t2++) {
        unsigned bh[4], bl[4];
        ldsm4(bh, sptr(&Bh[t2 * 16 + br][bc]));
        ldsm4(bl, sptr(&Bl[t2 * 16 + br][bc]));
        mma_bf16(acc[2 * t2],     ah, &bh[0]);
        mma_bf16(acc[2 * t2],     al, &bh[0]);
        mma_bf16(acc[2 * t2],     ah, &bl[0]);
        mma_bf16(acc[2 * t2 + 1], ah, &bh[2]);
        mma_bf16(acc[2 * t2 + 1], al, &bh[2]);
        mma_bf16(acc[2 * t2 + 1], ah, &bl[2]);
    }
}

// hi-only slab (bias GEMM): 1 MMA per n8 tile
template<int TN, int PA, int PB>
__device__ __forceinline__ void mma_k16_1(float (*acc)[4],
    const unsigned (*Ah)[PA], const unsigned (*Bh)[PB],
    int arow, int pb, int lane)
{
    const int ar = arow + (lane & 15);
    const int ac = pb + ((lane >> 4) << 2);
    unsigned ah[4];
    ldsm4(ah, sptr(&Ah[ar][ac]));
    const int br = (lane & 7) + ((lane & 16) >> 1);
    const int bc = pb + ((lane & 8) >> 1);
    #pragma unroll
    for (int t2 = 0; t2 < TN / 2; t2++) {
        unsigned bh[4];
        ldsm4(bh, sptr(&Bh[t2 * 16 + br][bc]));
        mma_bf16(acc[2 * t2],     ah, &bh[0]);
        mma_bf16(acc[2 * t2 + 1], ah, &bh[2]);
    }
}

__device__ __forceinline__ const float* v_row(int b, int h, int j) {
    return g_V + (size_t)(b * SEQ + h * HD + (j >> 4)) * DM + ((j & 15) << 6);
}

// ==================== pack kernels ====================
// row-major pack: 8 consecutive floats -> 4 hi pairs + 4 lo pairs
__global__ __launch_bounds__(256) void pack_rm(const float* __restrict__ src,
                                               unsigned* __restrict__ dh,
                                               unsigned* __restrict__ dl, int n8)
{
    const int i = blockIdx.x * 256 + threadIdx.x;
    if (i < n8) {
        const float4 a = ((const float4*)src)[2 * i], b = ((const float4*)src)[2 * i + 1];
        unsigned h0, l0, h1, l1, h2, l2, h3, l3;
        split2(make_float2(a.x, a.y), h0, l0);
        split2(make_float2(a.z, a.w), h1, l1);
        split2(make_float2(b.x, b.y), h2, l2);
        split2(make_float2(b.z, b.w), h3, l3);
        ((uint4*)dh)[i] = make_uint4(h0, h1, h2, h3);
        ((uint4*)dl)[i] = make_uint4(l0, l1, l2, l3);
    }
}

// col-major pack of weight W[1024][1024] -> out[c][kp] = pair(W[2kp][c], W[2kp+1][c])
// NOTE: staging pitch 68 (multiple of 4) keeps the float4 stores 16B-aligned.
__global__ __launch_bounds__(256) void pack_cm(const float* __restrict__ W,
                                               unsigned* __restrict__ dh,
                                               unsigned* __restrict__ dl)
{
    __shared__ float s[64][68];
    const int tid = threadIdx.x;
    const int k0 = blockIdx.y * 64, c0 = blockIdx.x * 64;
    #pragma unroll
    for (int it = 0; it < 4; it++) {
        const int idx = tid + it * 256;
        const int kr = idx >> 4, cc = (idx & 15) * 4;
        *(float4*)&s[kr][cc] = *(const float4*)(W + (size_t)(k0 + kr) * DM + c0 + cc);
    }
    __syncthreads();
    const int c = tid >> 2, ch = tid & 3;
    unsigned h[8], l[8];
    #pragma unroll
    for (int p = 0; p < 8; p++) {
        const int kp = ch * 8 + p;
        split2(make_float2(s[2 * kp][c], s[2 * kp + 1][c]), h[p], l[p]);
    }
    unsigned* oh = dh + (size_t)(c0 + c) * KP + (k0 >> 1) + ch * 8;
    unsigned* ol = dl + (size_t)(c0 + c) * KP + (k0 >> 1) + ch * 8;
    *(uint4*)oh       = make_uint4(h[0], h[1], h[2], h[3]);
    *(uint4*)(oh + 4) = make_uint4(h[4], h[5], h[6], h[7]);
    *(uint4*)ol       = make_uint4(l[0], l[1], l[2], l[3]);
    *(uint4*)(ol + 4) = make_uint4(l[4], l[5], l[6], l[7]);
}

// ==================== packed GEMM (cp.async 2-stage) ====================
__device__ __forceinline__ void mma32p(const unsigned (*Ah)[20], const unsigned (*Al)[20],
                                       const unsigned (*Bh)[20], const unsigned (*Bl)[20],
                                       float (*acc)[4][4], int warp_m, int warp_n, int lane) {
    #pragma unroll
    for (int s = 0; s < 2; s++) {
        const int pb = 8 * s;
        const int arl = lane & 15, acl = pb + ((lane >> 4) << 2);
        const int brl = (lane & 7) + ((lane & 16) >> 1), bcl = pb + ((lane & 8) >> 1);
        unsigned ah[4][4], al[4][4], bh[2][4], bl[2][4];
        #pragma unroll
        for (int tm = 0; tm < 4; tm++) {
            ldsm4(ah[tm], sptr(&Ah[warp_m + tm * 16 + arl][acl]));
            ldsm4(al[tm], sptr(&Al[warp_m + tm * 16 + arl][acl]));
        }
        #pragma unroll
        for (int t2 = 0; t2 < 2; t2++) {
            ldsm4(bh[t2], sptr(&Bh[warp_n + t2 * 16 + brl][bcl]));
            ldsm4(bl[t2], sptr(&Bl[warp_n + t2 * 16 + brl][bcl]));
        }
        #pragma unroll
        for (int tm = 0; tm < 4; tm++)
            #pragma unroll
            for (int t2 = 0; t2 < 2; t2++) {
                mma_bf16(acc[tm][2 * t2],     ah[tm], &bh[t2][0]);
                mma_bf16(acc[tm][2 * t2],     al[tm], &bh[t2][0]);
                mma_bf16(acc[tm][2 * t2],     ah[tm], &bl[t2][0]);
                mma_bf16(acc[tm][2 * t2 + 1], ah[tm], &bh[t2][2]);
                mma_bf16(acc[tm][2 * t2 + 1], al[tm], &bh[t2][2]);
                mma_bf16(acc[tm][2 * t2 + 1], ah[tm], &bl[t2][2]);
            }
    }
}

struct GSmem { unsigned A[2][2][128][20]; unsigned B[2][2][128][20]; };  // 80 KB

__global__ __launch_bounds__(256, 2) void gemm_pk(
    const unsigned* __restrict__ Agh, const unsigned* __restrict__ Agl,
    const unsigned* __restrict__ Bgh, const unsigned* __restrict__ Bgl,
    float* __restrict__ Cf, unsigned* __restrict__ Ch, unsigned* __restrict__ Cl)
{
    extern __shared__ char raw[];
    GSmem* sm = (GSmem*)raw;
    const int tid = threadIdx.x, lane = tid & 31, w = tid >> 5;
    const int m0 = blockIdx.y << 7, n0 = blockIdx.x << 7;
    const int warp_m = (w >> 2) * 64, warp_n = (w & 3) * 32;
    const int lrow = tid >> 1, loff = (tid & 1) << 3;
    const unsigned* Ash = Agh + (size_t)(m0 + lrow) * KP + loff;
    const unsigned* Asl = Agl + (size_t)(m0 + lrow) * KP + loff;
    const unsigned* Bsh = Bgh + (size_t)(n0 + lrow) * KP + loff;
    const unsigned* Bsl = Bgl + (size_t)(n0 + lrow) * KP + loff;

    auto load = [&](int s, int st) {
        const int kp0 = s << 4;
        cpa16(sptr(&sm->A[st][0][lrow][loff]),     Ash + kp0);
        cpa16(sptr(&sm->A[st][0][lrow][loff + 4]), Ash + kp0 + 4);
        cpa16(sptr(&sm->A[st][1][lrow][loff]),     Asl + kp0);
        cpa16(sptr(&sm->A[st][1][lrow][loff + 4]), Asl + kp0 + 4);
        cpa16(sptr(&sm->B[st][0][lrow][loff]),     Bsh + kp0);
        cpa16(sptr(&sm->B[st][0][lrow][loff + 4]), Bsh + kp0 + 4);
        cpa16(sptr(&sm->B[st][1][lrow][loff]),     Bsl + kp0);
        cpa16(sptr(&sm->B[st][1][lrow][loff + 4]), Bsl + kp0 + 4);
        asm volatile("cp.async.commit_group;" ::: "memory");
    };

    float acc[4][4][4] = {};
    load(0, 0);
    for (int s = 0; s < 32; s++) {
        const int st = s & 1;
        if (s < 31) {
            load(s + 1, st ^ 1);
            asm volatile("cp.async.wait_group 1;" ::: "memory");
        } else {
            asm volatile("cp.async.wait_group 0;" ::: "memory");
        }
        __syncthreads();
        mma32p(sm->A[st][0], sm->A[st][1], sm->B[st][0], sm->B[st][1],
               acc, warp_m, warp_n, lane);
        __syncthreads();
    }

    const int qr = lane >> 2, qc = lane & 3;
    if (Cf) {
        #pragma unroll
        for (int tm = 0; tm < 4; tm++)
            #pragma unroll
            for (int tn = 0; tn < 4; tn++) {
                const int r = m0 + warp_m + tm * 16 + qr;
                const int cN = n0 + warp_n + tn * 8 + qc * 2;
                *(float2*)(Cf + (size_t)r * DM + cN)       = make_float2(acc[tm][tn][0], acc[tm][tn][1]);
                *(float2*)(Cf + (size_t)(r + 8) * DM + cN) = make_float2(acc[tm][tn][2], acc[tm][tn][3]);
            }
    } else {
        #pragma unroll
        for (int tm = 0; tm < 4; tm++)
            #pragma unroll
            for (int tn = 0; tn < 4; tn++) {
                const int r = m0 + warp_m + tm * 16 + qr;
                const int pidx = ((n0 + warp_n) >> 1) + tn * 4 + qc;
                unsigned hh, ll;
                split2(make_float2(acc[tm][tn][0], acc[tm][tn][1]), hh, ll);
                Ch[(size_t)r * KP + pidx] = hh; Cl[(size_t)r * KP + pidx] = ll;
                split2(make_float2(acc[tm][tn][2], acc[tm][tn][3]), hh, ll);
                Ch[(size_t)(r + 8) * KP + pidx] = hh; Cl[(size_t)(r + 8) * KP + pidx] = ll;
            }
    }
}

// ==================== fused flash attention with relative bias (512 threads) ====================
struct FSmem {
    unsigned Qh[129][36], Ql[129][36];   // Q rows i0..i0+128 (129 for the +1 shift)
    unsigned Kh[128][36], Kl[128][36];   // K^T tile: [j][dd-pair]
    unsigned Eh[128][36];                // Er window (hi-only)
    unsigned Vh[64][68],  Vl[64][68];    // V tile: [dd][j-pair]
    union {
        float G[128][132];                                 // rel-bias staging
        struct { unsigned Ph[128][68], Pl[128][68]; } pp;  // softmaxed P operand
    } u;
    float redmax[128][2];
    float redsum[128][2];
};

__global__ __launch_bounds__(512, 1) void flash_kernel()
{
    extern __shared__ char raw[];
    FSmem* sm = (FSmem*)raw;
    const int tid = threadIdx.x, lane = tid & 31, w = tid >> 5;   // 16 warps
    const int qr = lane >> 2, qc = lane & 3;
    const int rg = w & 7, cg = w >> 3;
    const int rg16 = rg << 4;
    const int bh = blockIdx.y, b = bh >> 4, h = bh & 15;
    const int i0 = blockIdx.x << 7;

    // ---- load Q (packed copy): 129 rows x 4 chunks of 8 pairs ----
    #pragma unroll
    for (int it = 0; it < 2; it++) {
        const int idx = tid + it * 512;
        if (idx < 129 * 4) {
            const int r = idx >> 2, ch = idx & 3;
            const int i = i0 + r;
            if (i < SEQ) {
                const size_t base = (size_t)(b * SEQ + h * HD + (i >> 4)) * KP + ((i & 15) << 5) + ch * 8;
                *(uint4*)&sm->Qh[r][ch * 8]     = *(const uint4*)(g_Qh + base);
                *(uint4*)&sm->Qh[r][ch * 8 + 4] = *(const uint4*)(g_Qh + base + 4);
                *(uint4*)&sm->Ql[r][ch * 8]     = *(const uint4*)(g_Ql + base);
                *(uint4*)&sm->Ql[r][ch * 8 + 4] = *(const uint4*)(g_Ql + base + 4);
            } else {
                const uint4 z = make_uint4(0, 0, 0, 0);
                *(uint4*)&sm->Qh[r][ch * 8] = z; *(uint4*)&sm->Qh[r][ch * 8 + 4] = z;
                *(uint4*)&sm->Ql[r][ch * 8] = z; *(uint4*)&sm->Ql[r][ch * 8 + 4] = z;
            }
        }
    }

    float accO[4][4] = {};
    float m0 = -1e30f, m1 = -1e30f, l0 = 0.f, l1 = 0.f;
    const float* kbase = g_K + (size_t)(b * SEQ + h * HD) * DM;

    for (int jt = 0; jt < 8; jt++) {
        const int j0 = jt << 7;
        const int delta = j0 - i0;
        float accS[8][4] = {};

        // ---- relative-bias phases ----
        #pragma unroll 1
        for (int band = 0; band < 2; band++) {
            if (band == 0 && delta > 0) continue;
            if (band == 1 && delta < 0) continue;
            const int ebase = (band == 0) ? (895 + delta) : (delta - 130);
            #pragma unroll 1
            for (int half = 0; half < 2; half++) {
                if (band == 1 && half == 0 && delta < 128) continue;
                {   // load Er window half (packed hi copy)
                    const int r = tid >> 2, ch = tid & 3;
                    const int er = ebase + half * 128 + r;
                    if (er >= 0 && er < SEQ) {
                        const unsigned* pe = g_Eh + (size_t)er * 32 + ch * 8;
                        *(uint4*)&sm->Eh[r][ch * 8]     = *(const uint4*)pe;
                        *(uint4*)&sm->Eh[r][ch * 8 + 4] = *(const uint4*)(pe + 4);
                    } else {
                        const uint4 z = make_uint4(0, 0, 0, 0);
                        *(uint4*)&sm->Eh[r][ch * 8] = z; *(uint4*)&sm->Eh[r][ch * 8 + 4] = z;
                    }
                }
                __syncthreads();
                const int arow = rg16 + band;
                #pragma unroll 1
                for (int nh = 0; nh < 2; nh++) {
                    float gacc[4][4] = {};
                    const unsigned (*Ehp)[36] = (const unsigned (*)[36])&sm->Eh[cg * 64 + nh * 32];
                    #pragma unroll
                    for (int pb = 0; pb < 32; pb += 8)
                        mma_k16_1<4, 36, 36>(gacc, sm->Qh, Ehp, arow, pb, lane);
                    #pragma unroll
                    for (int tn = 0; tn < 4; tn++) {
                        const int r = rg16 + qr, c = cg * 64 + nh * 32 + tn * 8 + qc * 2;
                        *(float2*)&sm->u.G[r][c]     = make_float2(gacc[tn][0], gacc[tn][1]);
                        *(float2*)&sm->u.G[r + 8][c] = make_float2(gacc[tn][2], gacc[tn][3]);
                    }
                }
                __syncthreads();
                #pragma unroll
                for (int tn = 0; tn < 8; tn++)
                    #pragma unroll
                    for (int k = 0; k < 4; k++) {
                        const int r = rg16 + qr + ((k >> 1) << 3);
                        const int jc = cg * 64 + tn * 8 + qc * 2 + (k & 1);
                        const int diff = jc - r;
                        const bool cond = (band == 0) ? (diff <= -delta) : (diff >= 2 - delta);
                        const int mm = 128 + diff - half * 128;
                        if (cond && mm >= 0 && mm < 128) accS[tn][k] += sm->u.G[r][mm];
                    }
            }
        }

        // ---- load K^T and V tiles ----
        #pragma unroll
        for (int it = 0; it < 2; it++) {
            const int idx = tid + it * 512;
            const int kp = idx & 31, cgl = idx >> 5;
            const float* p = kbase + (size_t)(2 * kp) * DM + j0 + cgl * 4;
            st_km2x4<36>(*(const float4*)p, *(const float4*)(p + DM), sm->Kh, sm->Kl, cgl * 4, kp);
        }
        #pragma unroll
        for (int it = 0; it < 2; it++) {
            const int idx = tid + it * 512;
            const int jp = idx & 63, cgl = idx >> 6;
            const float4 x0 = *(const float4*)(v_row(b, h, j0 + 2 * jp)     + cgl * 4);
            const float4 x1 = *(const float4*)(v_row(b, h, j0 + 2 * jp + 1) + cgl * 4);
            st_km2x4<68>(x0, x1, sm->Vh, sm->Vl, cgl * 4, jp);
        }
        __syncthreads();

        // ---- q @ k^T accumulate on top of rel ----
        {
            const unsigned (*Khp)[36] = (const unsigned (*)[36])&sm->Kh[cg * 64];
            const unsigned (*Klp)[36] = (const unsigned (*)[36])&sm->Kl[cg * 64];
            #pragma unroll
            for (int pb = 0; pb < 32; pb += 8)
                mma_k16_3<8, 36, 36>(accS, sm->Qh, sm->Ql, Khp, Klp, rg16, pb, lane);
        }

        // ---- online softmax ----
        float tm0 = -1e30f, tm1 = -1e30f;
        #pragma unroll
        for (int tn = 0; tn < 8; tn++) {
            tm0 = fmaxf(tm0, fmaxf(accS[tn][0], accS[tn][1]));
            tm1 = fmaxf(tm1, fmaxf(accS[tn][2], accS[tn][3]));
        }
        tm0 = fmaxf(tm0, __shfl_xor_sync(0xffffffffu, tm0, 1));
        tm0 = fmaxf(tm0, __shfl_xor_sync(0xffffffffu, tm0, 2));
        tm1 = fmaxf(tm1, __shfl_xor_sync(0xffffffffu, tm1, 1));
        tm1 = fmaxf(tm1, __shfl_xor_sync(0xffffffffu, tm1, 2));
        tm0 *= 0.125f; tm1 *= 0.125f;
        if (qc == 0) {
            sm->redmax[rg16 + qr][cg]     = tm0;
            sm->redmax[rg16 + qr + 8][cg] = tm1;
        }
        __syncthreads();
        const float cm0 = fmaxf(sm->redmax[rg16 + qr][0],     sm->redmax[rg16 + qr][1]);
        const float cm1 = fmaxf(sm->redmax[rg16 + qr + 8][0], sm->redmax[rg16 + qr + 8][1]);
        const float nm0 = fmaxf(m0, cm0), nm1 = fmaxf(m1, cm1);
        const float f0 = __expf(m0 - nm0), f1 = __expf(m1 - nm1);
        float s0 = 0.f, s1 = 0.f;
        #pragma unroll
        for (int tn = 0; tn < 8; tn++) {
            accS[tn][0] = __expf(accS[tn][0] * 0.125f - nm0); s0 += accS[tn][0];
            accS[tn][1] = __expf(accS[tn][1] * 0.125f - nm0); s0 += accS[tn][1];
            accS[tn][2] = __expf(accS[tn][2] * 0.125f - nm1); s1 += accS[tn][2];
            accS[tn][3] = __expf(accS[tn][3] * 0.125f - nm1); s1 += accS[tn][3];
        }
        s0 += __shfl_xor_sync(0xffffffffu, s0, 1); s0 += __shfl_xor_sync(0xffffffffu, s0, 2);
        s1 += __shfl_xor_sync(0xffffffffu, s1, 1); s1 += __shfl_xor_sync(0xffffffffu, s1, 2);
        if (qc == 0) {
            sm->redsum[rg16 + qr][cg]     = s0;
            sm->redsum[rg16 + qr + 8][cg] = s1;
        }

        // ---- write split-bf16 P operand ----
        #pragma unroll
        for (int tn = 0; tn < 8; tn++) {
            unsigned hh, ll;
            split2(make_float2(accS[tn][0], accS[tn][1]), hh, ll);
            sm->u.pp.Ph[rg16 + qr][cg * 32 + tn * 4 + qc] = hh;
            sm->u.pp.Pl[rg16 + qr][cg * 32 + tn * 4 + qc] = ll;
            split2(make_float2(accS[tn][2], accS[tn][3]), hh, ll);
            sm->u.pp.Ph[rg16 + qr + 8][cg * 32 + tn * 4 + qc] = hh;
            sm->u.pp.Pl[rg16 + qr + 8][cg * 32 + tn * 4 + qc] = ll;
        }
        __syncthreads();

        const float cs0 = sm->redsum[rg16 + qr][0]     + sm->redsum[rg16 + qr][1];
        const float cs1 = sm->redsum[rg16 + qr + 8][0] + sm->redsum[rg16 + qr + 8][1];
        l0 = l0 * f0 + cs0; l1 = l1 * f1 + cs1; m0 = nm0; m1 = nm1;
        #pragma unroll
        for (int tn2 = 0; tn2 < 4; tn2++) {
            accO[tn2][0] *= f0; accO[tn2][1] *= f0;
            accO[tn2][2] *= f1; accO[tn2][3] *= f1;
        }

        // ---- accO += P @ V ----
        {
            const unsigned (*Vhp)[68] = (const unsigned (*)[68])&sm->Vh[cg * 32];
            const unsigned (*Vlp)[68] = (const unsigned (*)[68])&sm->Vl[cg * 32];
            #pragma unroll
            for (int pb = 0; pb < 64; pb += 8)
                mma_k16_3<4, 68, 68>(accO, sm->u.pp.Ph, sm->u.pp.Pl, Vhp, Vlp, rg16, pb, lane);
        }
    }

    // ---- epilogue: normalize, pack split-bf16, write O ----
    const float inv0 = 1.f / l0, inv1 = 1.f / l1;
    #pragma unroll
    for (int tn2 = 0; tn2 < 4; tn2++) {
        const int r = i0 + rg16 + qr;
        const int pidx = h * 32 + cg * 16 + tn2 * 4 + qc;
        unsigned hh, ll;
        split2(make_float2(accO[tn2][0] * inv0, accO[tn2][1] * inv0), hh, ll);
        g_Oh[(size_t)(b * SEQ + r) * KP + pidx] = hh;
        g_Ol[(size_t)(b * SEQ + r) * KP + pidx] = ll;
        split2(make_float2(accO[tn2][2] * inv1, accO[tn2][3] * inv1), hh, ll);
        g_Oh[(size_t)(b * SEQ + r + 8) * KP + pidx] = hh;
        g_Ol[(size_t)(b * SEQ + r + 8) * KP + pidx] = ll;
    }
}

// ---------------- launch ----------------
extern "C" void kernel_launch(void* const* d_in, const int* in_sizes, int n_in,
                              void* d_out, int out_size)
{
    const float* query = (const float*)d_in[0];
    const float* key   = (const float*)d_in[1];
    const float* value = (const float*)d_in[2];
    const float* WQ    = (const float*)d_in[3];
    const float* WK    = (const float*)d_in[4];
    const float* WV    = (const float*)d_in[5];
    const float* Er    = (const float*)d_in[6];
    const float* WM    = (const float*)d_in[7];
    float* out = (float*)d_out;

    static unsigned *inh = nullptr, *inl, *wh, *wl, *Qh, *Ql, *Oh, *Ol, *Eh, *El;
    static float *pK, *pV;
    if (!inh) {
        cudaGetSymbolAddress((void**)&inh, g_inh);
        cudaGetSymbolAddress((void**)&inl, g_inl);
        cudaGetSymbolAddress((void**)&wh,  g_wh);
        cudaGetSymbolAddress((void**)&wl,  g_wl);
        cudaGetSymbolAddress((void**)&Qh,  g_Qh);
        cudaGetSymbolAddress((void**)&Ql,  g_Ql);
        cudaGetSymbolAddress((void**)&Oh,  g_Oh);
        cudaGetSymbolAddress((void**)&Ol,  g_Ol);
        cudaGetSymbolAddress((void**)&Eh,  g_Eh);
        cudaGetSymbolAddress((void**)&El,  g_El);
        cudaGetSymbolAddress((void**)&pK,  g_K);
        cudaGetSymbolAddress((void**)&pV,  g_V);
        cudaFuncSetAttribute(flash_kernel, cudaFuncAttributeMaxDynamicSharedMemorySize,
                             (int)sizeof(FSmem));
        cudaFuncSetAttribute(gemm_pk, cudaFuncAttributeMaxDynamicSharedMemorySize,
                             (int)sizeof(GSmem));
    }

    const int IN8 = MTOK * DM / 8;          // 524288
    const unsigned OFF = (unsigned)MTOK * KP;
    const unsigned WOFF = (unsigned)DM * KP;
    const dim3 gG(DM / 128, MTOK / 128);    // (8, 32)

    pack_rm<<<IN8 / 256, 256>>>(query, inh,            inl,            IN8);
    pack_rm<<<IN8 / 256, 256>>>(key,   inh + OFF,      inl + OFF,      IN8);
    pack_rm<<<IN8 / 256, 256>>>(value, inh + 2 * OFF,  inl + 2 * OFF,  IN8);
    pack_rm<<<(SEQ * HD / 8) / 256, 256>>>(Er, Eh, El, SEQ * HD / 8);
    pack_cm<<<dim3(16, 16), 256>>>(WQ, wh,            wl);
    pack_cm<<<dim3(16, 16), 256>>>(WK, wh + WOFF,     wl + WOFF);
    pack_cm<<<dim3(16, 16), 256>>>(WV, wh + 2 * WOFF, wl + 2 * WOFF);
    pack_cm<<<dim3(16, 16), 256>>>(WM, wh + 3 * WOFF, wl + 3 * WOFF);

    gemm_pk<<<gG, 256, sizeof(GSmem)>>>(inh,           inl,           wh,            wl,            nullptr, Qh, Ql);
    gemm_pk<<<gG, 256, sizeof(GSmem)>>>(inh + OFF,     inl + OFF,     wh + WOFF,     wl + WOFF,     pK, nullptr, nullptr);
    gemm_pk<<<gG, 256, sizeof(GSmem)>>>(inh + 2 * OFF, inl + 2 * OFF, wh + 2 * WOFF, wl + 2 * WOFF, pV, nullptr, nullptr);
    flash_kernel<<<dim3(SEQ / 128, BH), dim3(512), sizeof(FSmem)>>>();
    gemm_pk<<<gG, 256, sizeof(GSmem)>>>(Oh, Ol, wh + 3 * WOFF, wl + 3 * WOFF, out, nullptr, nullptr);
}

// round 12
// speedup vs baseline: 1.3696x; 1.0229x over previous
#include <cuda_runtime.h>
#include <cuda_bf16.h>

#define BATCH 4
#define SEQ   1024
#define DM    1024
#define HEADS 16
#define HD    64
#define BH    (BATCH*HEADS)
#define MTOK  (BATCH*SEQ)          // 4096
#define KP    (DM/2)               // 512 packed pairs per row
#define OFFIN ((unsigned)MTOK*KP)
#define WOFF  ((unsigned)DM*KP)

// ---------------- scratch (device globals; no allocs allowed) ----------------
__device__ unsigned g_inh[3u*MTOK*KP], g_inl[3u*MTOK*KP];   // packed inputs (q,k,v)
__device__ unsigned g_wh[4u*DM*KP],   g_wl[4u*DM*KP];       // packed weights (col-major)
__device__ unsigned g_Qh[MTOK*KP],    g_Ql[MTOK*KP];        // packed Q projection (pre-scaled by 1/8)
__device__ float    g_K[MTOK*DM],     g_V[MTOK*DM];         // fp32 K,V projections
__device__ unsigned g_Oh[MTOK*KP],    g_Ol[MTOK*KP];        // packed attention out
__device__ unsigned g_Eh[SEQ*(HD/2)], g_El[SEQ*(HD/2)];     // packed Er (hi used)

// ---------------- helpers ----------------
__device__ __forceinline__ void split2(float2 v, unsigned &h, unsigned &l) {
    __nv_bfloat162 bh = __float22bfloat162_rn(v);
    float2 back = __bfloat1622float2(bh);
    __nv_bfloat162 bl = __float22bfloat162_rn(make_float2(v.x - back.x, v.y - back.y));
    h = *(unsigned*)&bh;
    l = *(unsigned*)&bl;
}

__device__ __forceinline__ unsigned sptr(const void* p) {
    return (unsigned)__cvta_generic_to_shared(p);
}

__device__ __forceinline__ void cpa16(unsigned dst, const void* src) {
    asm volatile("cp.async.cg.shared.global [%0], [%1], 16;" :: "r"(dst), "l"(src) : "memory");
}

__device__ __forceinline__ void ldsm4(unsigned r[4], unsigned a) {
    asm volatile("ldmatrix.sync.aligned.m8n8.x4.shared.b16 {%0,%1,%2,%3}, [%4];"
        : "=r"(r[0]), "=r"(r[1]), "=r"(r[2]), "=r"(r[3]) : "r"(a));
}

__device__ __forceinline__ void mma_bf16(float c[4], const unsigned a[4], const unsigned b[2]) {
    asm volatile(
        "mma.sync.aligned.m16n8k16.row.col.f32.bf16.bf16.f32 "
        "{%0,%1,%2,%3},{%4,%5,%6,%7},{%8,%9},{%0,%1,%2,%3};\n"
        : "+f"(c[0]), "+f"(c[1]), "+f"(c[2]), "+f"(c[3])
        : "r"(a[0]), "r"(a[1]), "r"(a[2]), "r"(a[3]), "r"(b[0]), "r"(b[1]));
}

// store a 2(k)x4(n) chunk from two k-rows into col-major B operand (scalar stores)
template<int P>
__device__ __forceinline__ void st_km2x4(float4 x0, float4 x1, unsigned (*H)[P],
                                         unsigned (*L)[P], int c, int kp) {
    unsigned h, l;
    split2(make_float2(x0.x, x1.x), h, l); H[c][kp] = h;     L[c][kp] = l;
    split2(make_float2(x0.y, x1.y), h, l); H[c + 1][kp] = h; L[c + 1][kp] = l;
    split2(make_float2(x0.z, x1.z), h, l); H[c + 2][kp] = h; L[c + 2][kp] = l;
    split2(make_float2(x0.w, x1.w), h, l); H[c + 3][kp] = h; L[c + 3][kp] = l;
}

// one k16 slab (pair base pb), TN n8-tiles (TN even), 3-term split MMA, ldmatrix feeds.
template<int TN, int PA, int PB>
__device__ __forceinline__ void mma_k16_3(float (*acc)[4],
    const unsigned (*Ah)[PA], const unsigned (*Al)[PA],
    const unsigned (*Bh)[PB], const unsigned (*Bl)[PB],
    int arow, int pb, int lane)
{
    const int ar = arow + (lane & 15);
    const int ac = pb + ((lane >> 4) << 2);
    unsigned ah[4], al[4];
    ldsm4(ah, sptr(&Ah[ar][ac]));
    ldsm4(al, sptr(&Al[ar][ac]));
    const int br = (lane & 7) + ((lane & 16) >> 1);
    const int bc = pb + ((lane & 8) >> 1);
    #pragma unroll
    for (int t2 = 0; t2 < TN / 2; t2++) {
        unsigned bh[4], bl[4];
        ldsm4(bh, sptr(&Bh[t2 * 16 + br][bc]));
        ldsm4(bl, sptr(&Bl[t2 * 16 + br][bc]));
        mma_bf16(acc[2 * t2],     ah, &bh[0]);
        mma_bf16(acc[2 * t2],     al, &bh[0]);
        mma_bf16(acc[2 * t2],     ah, &bl[0]);
        mma_bf16(acc[2 * t2 + 1], ah, &bh[2]);
        mma_bf16(acc[2 * t2 + 1], al, &bh[2]);
        mma_bf16(acc[2 * t2 + 1], ah, &bl[2]);
    }
}

// hi-only slab (bias GEMM): 1 MMA per n8 tile
template<int TN, int PA, int PB>
__device__ __forceinline__ void mma_k16_1(float (*acc)[4],
    const unsigned (*Ah)[PA], const unsigned (*Bh)[PB],
    int arow, int pb, int lane)
{
    const int ar = arow + (lane & 15);
    const int ac = pb + ((lane >> 4) << 2);
    unsigned ah[4];
    ldsm4(ah, sptr(&Ah[ar][ac]));
    const int br = (lane & 7) + ((lane & 16) >> 1);
    const int bc = pb + ((lane & 8) >> 1);
    #pragma unroll
    for (int t2 = 0; t2 < TN / 2; t2++) {
        unsigned bh[4];
        ldsm4(bh, sptr(&Bh[t2 * 16 + br][bc]));
        mma_bf16(acc[2 * t2],     ah, &bh[0]);
        mma_bf16(acc[2 * t2 + 1], ah, &bh[2]);
    }
}

__device__ __forceinline__ const float* v_row(int b, int h, int j) {
    return g_V + (size_t)(b * SEQ + h * HD + (j >> 4)) * DM + ((j & 15) << 6);
}

// ==================== pack kernels ====================
// row-major pack of q/k/v (z selects tensor): 8 floats -> 4 hi + 4 lo pairs
__global__ __launch_bounds__(256) void pack_rm3(const float* __restrict__ s0,
                                                const float* __restrict__ s1,
                                                const float* __restrict__ s2)
{
    const int z = blockIdx.y;
    const float* src = (z == 0) ? s0 : (z == 1) ? s1 : s2;
    unsigned* dh = g_inh + (unsigned)z * OFFIN;
    unsigned* dl = g_inl + (unsigned)z * OFFIN;
    const int i = blockIdx.x * 256 + threadIdx.x;
    const float4 a = ((const float4*)src)[2 * i], b = ((const float4*)src)[2 * i + 1];
    unsigned h0, l0, h1, l1, h2, l2, h3, l3;
    split2(make_float2(a.x, a.y), h0, l0);
    split2(make_float2(a.z, a.w), h1, l1);
    split2(make_float2(b.x, b.y), h2, l2);
    split2(make_float2(b.z, b.w), h3, l3);
    ((uint4*)dh)[i] = make_uint4(h0, h1, h2, h3);
    ((uint4*)dl)[i] = make_uint4(l0, l1, l2, l3);
}

__global__ __launch_bounds__(256) void pack_er(const float* __restrict__ Er, int n8)
{
    const int i = blockIdx.x * 256 + threadIdx.x;
    if (i < n8) {
        const float4 a = ((const float4*)Er)[2 * i], b = ((const float4*)Er)[2 * i + 1];
        unsigned h0, l0, h1, l1, h2, l2, h3, l3;
        split2(make_float2(a.x, a.y), h0, l0);
        split2(make_float2(a.z, a.w), h1, l1);
        split2(make_float2(b.x, b.y), h2, l2);
        split2(make_float2(b.z, b.w), h3, l3);
        ((uint4*)g_Eh)[i] = make_uint4(h0, h1, h2, h3);
        ((uint4*)g_El)[i] = make_uint4(l0, l1, l2, l3);
    }
}

// col-major pack of 4 weights (z selects): out[c][kp] = pair(W[2kp][c], W[2kp+1][c])
__global__ __launch_bounds__(256) void pack_cm4(const float* __restrict__ W0,
                                                const float* __restrict__ W1,
                                                const float* __restrict__ W2,
                                                const float* __restrict__ W3)
{
    __shared__ float s[64][68];   // pitch 68: float4 stores stay 16B-aligned
    const int z = blockIdx.z;
    const float* W = (z == 0) ? W0 : (z == 1) ? W1 : (z == 2) ? W2 : W3;
    unsigned* dh = g_wh + (unsigned)z * WOFF;
    unsigned* dl = g_wl + (unsigned)z * WOFF;
    const int tid = threadIdx.x;
    const int k0 = blockIdx.y * 64, c0 = blockIdx.x * 64;
    #pragma unroll
    for (int it = 0; it < 4; it++) {
        const int idx = tid + it * 256;
        const int kr = idx >> 4, cc = (idx & 15) * 4;
        *(float4*)&s[kr][cc] = *(const float4*)(W + (size_t)(k0 + kr) * DM + c0 + cc);
    }
    __syncthreads();
    const int c = tid >> 2, ch = tid & 3;
    unsigned h[8], l[8];
    #pragma unroll
    for (int p = 0; p < 8; p++) {
        const int kp = ch * 8 + p;
        split2(make_float2(s[2 * kp][c], s[2 * kp + 1][c]), h[p], l[p]);
    }
    unsigned* oh = dh + (size_t)(c0 + c) * KP + (k0 >> 1) + ch * 8;
    unsigned* ol = dl + (size_t)(c0 + c) * KP + (k0 >> 1) + ch * 8;
    *(uint4*)oh       = make_uint4(h[0], h[1], h[2], h[3]);
    *(uint4*)(oh + 4) = make_uint4(h[4], h[5], h[6], h[7]);
    *(uint4*)ol       = make_uint4(l[0], l[1], l[2], l[3]);
    *(uint4*)(ol + 4) = make_uint4(l[4], l[5], l[6], l[7]);
}

// ==================== packed GEMM: 4-stage cp.async ring, BK=16 ====================
struct GSmem { unsigned A[4][2][128][12]; unsigned B[4][2][128][12]; };   // 96 KB

// one BK=16 slab of the 128x128 block tile
__device__ __forceinline__ void mma16p(const unsigned (*Ah)[12], const unsigned (*Al)[12],
                                       const unsigned (*Bh)[12], const unsigned (*Bl)[12],
                                       float (*acc)[4][4], int warp_m, int warp_n, int lane) {
    const int arl = lane & 15, acl = (lane >> 4) << 2;
    const int brl = (lane & 7) + ((lane & 16) >> 1), bcl = (lane & 8) >> 1;
    unsigned ah[4][4], al[4][4], bh[2][4], bl[2][4];
    #pragma unroll
    for (int tm = 0; tm < 4; tm++) {
        ldsm4(ah[tm], sptr(&Ah[warp_m + tm * 16 + arl][acl]));
        ldsm4(al[tm], sptr(&Al[warp_m + tm * 16 + arl][acl]));
    }
    #pragma unroll
    for (int t2 = 0; t2 < 2; t2++) {
        ldsm4(bh[t2], sptr(&Bh[warp_n + t2 * 16 + brl][bcl]));
        ldsm4(bl[t2], sptr(&Bl[warp_n + t2 * 16 + brl][bcl]));
    }
    #pragma unroll
    for (int tm = 0; tm < 4; tm++)
        #pragma unroll
        for (int t2 = 0; t2 < 2; t2++) {
            mma_bf16(acc[tm][2 * t2],     ah[tm], &bh[t2][0]);
            mma_bf16(acc[tm][2 * t2],     al[tm], &bh[t2][0]);
            mma_bf16(acc[tm][2 * t2],     ah[tm], &bl[t2][0]);
            mma_bf16(acc[tm][2 * t2 + 1], ah[tm], &bh[t2][2]);
            mma_bf16(acc[tm][2 * t2 + 1], al[tm], &bh[t2][2]);
            mma_bf16(acc[tm][2 * t2 + 1], ah[tm], &bl[t2][2]);
        }
}

// core GEMM body over packed operands; writes either float C or packed C (with scale)
__device__ __forceinline__ void gemm_body(
    const unsigned* Agh, const unsigned* Agl,
    const unsigned* Bgh, const unsigned* Bgl,
    float* Cf, unsigned* Ch, unsigned* Cl, float cscale,
    GSmem* sm, int m0, int n0)
{
    const int tid = threadIdx.x, lane = tid & 31, w = tid >> 5;
    const int warp_m = (w >> 2) * 64, warp_n = (w & 3) * 32;
    const int lrow = tid >> 1, loff = (tid & 1) << 2;
    const unsigned* Ash = Agh + (size_t)(m0 + lrow) * KP + loff;
    const unsigned* Asl = Agl + (size_t)(m0 + lrow) * KP + loff;
    const unsigned* Bsh = Bgh + (size_t)(n0 + lrow) * KP + loff;
    const unsigned* Bsl = Bgl + (size_t)(n0 + lrow) * KP + loff;

    auto load = [&](int s, int st) {
        const int kp0 = s << 3;
        cpa16(sptr(&sm->A[st][0][lrow][loff]), Ash + kp0);
        cpa16(sptr(&sm->A[st][1][lrow][loff]), Asl + kp0);
        cpa16(sptr(&sm->B[st][0][lrow][loff]), Bsh + kp0);
        cpa16(sptr(&sm->B[st][1][lrow][loff]), Bsl + kp0);
        asm volatile("cp.async.commit_group;" ::: "memory");
    };

    float acc[4][4][4] = {};
    load(0, 0); load(1, 1); load(2, 2);
    for (int s = 0; s < 64; s++) {
        const int st = s & 3;
        asm volatile("cp.async.wait_group 2;" ::: "memory");
        __syncthreads();
        if (s < 61) load(s + 3, (s + 3) & 3);
        else        asm volatile("cp.async.commit_group;" ::: "memory");
        mma16p(sm->A[st][0], sm->A[st][1], sm->B[st][0], sm->B[st][1],
               acc, warp_m, warp_n, lane);
    }

    const int qr = lane >> 2, qc = lane & 3;
    if (Cf) {
        #pragma unroll
        for (int tm = 0; tm < 4; tm++)
            #pragma unroll
            for (int tn = 0; tn < 4; tn++) {
                const int r = m0 + warp_m + tm * 16 + qr;
                const int cN = n0 + warp_n + tn * 8 + qc * 2;
                *(float2*)(Cf + (size_t)r * DM + cN)       = make_float2(acc[tm][tn][0], acc[tm][tn][1]);
                *(float2*)(Cf + (size_t)(r + 8) * DM + cN) = make_float2(acc[tm][tn][2], acc[tm][tn][3]);
            }
    } else {
        #pragma unroll
        for (int tm = 0; tm < 4; tm++)
            #pragma unroll
            for (int tn = 0; tn < 4; tn++) {
                const int r = m0 + warp_m + tm * 16 + qr;
                const int pidx = ((n0 + warp_n) >> 1) + tn * 4 + qc;
                unsigned hh, ll;
                split2(make_float2(acc[tm][tn][0] * cscale, acc[tm][tn][1] * cscale), hh, ll);
                Ch[(size_t)r * KP + pidx] = hh; Cl[(size_t)r * KP + pidx] = ll;
                split2(make_float2(acc[tm][tn][2] * cscale, acc[tm][tn][3] * cscale), hh, ll);
                Ch[(size_t)(r + 8) * KP + pidx] = hh; Cl[(size_t)(r + 8) * KP + pidx] = ll;
            }
    }
}

// fused QKV projections: z = 0 (Q, packed out, pre-scaled 1/8), 1 (K, fp32), 2 (V, fp32)
__global__ __launch_bounds__(256, 2) void gemm_qkv()
{
    extern __shared__ char raw[];
    const int z = blockIdx.z;
    const unsigned* Agh = g_inh + (unsigned)z * OFFIN;
    const unsigned* Agl = g_inl + (unsigned)z * OFFIN;
    const unsigned* Bgh = g_wh + (unsigned)z * WOFF;
    const unsigned* Bgl = g_wl + (unsigned)z * WOFF;
    float* Cf = (z == 1) ? g_K : (z == 2) ? g_V : nullptr;
    gemm_body(Agh, Agl, Bgh, Bgl, Cf, g_Qh, g_Ql, 0.125f,
              (GSmem*)raw, blockIdx.y << 7, blockIdx.x << 7);
}

__global__ __launch_bounds__(256, 2) void gemm_merge(float* __restrict__ out)
{
    extern __shared__ char raw[];
    gemm_body(g_Oh, g_Ol, g_wh + 3u * WOFF, g_wl + 3u * WOFF, out, nullptr, nullptr, 1.f,
              (GSmem*)raw, blockIdx.y << 7, blockIdx.x << 7);
}

// ==================== fused flash attention with relative bias (512 threads) ====================
struct FSmem {
    unsigned Qh[129][36], Ql[129][36];   // Q rows i0..i0+128 (129 for the +1 shift), pre-scaled 1/8
    unsigned Kh[128][36], Kl[128][36];   // K^T tile: [j][dd-pair]
    unsigned Eh[128][36];                // Er window (hi-only)
    unsigned Vh[64][68],  Vl[64][68];    // V tile: [dd][j-pair]
    union {
        float G[128][132];                                 // rel-bias staging
        struct { unsigned Ph[128][68], Pl[128][68]; } pp;  // softmaxed P operand
    } u;
    float redmax[128][2];
    float redsum[128][2];
};

__global__ __launch_bounds__(512, 1) void flash_kernel()
{
    extern __shared__ char raw[];
    FSmem* sm = (FSmem*)raw;
    const int tid = threadIdx.x, lane = tid & 31, w = tid >> 5;   // 16 warps
    const int qr = lane >> 2, qc = lane & 3;
    const int rg = w & 7, cg = w >> 3;
    const int rg16 = rg << 4;
    const int bh = blockIdx.y, b = bh >> 4, h = bh & 15;
    const int i0 = blockIdx.x << 7;

    // ---- load Q (packed copy): 129 rows x 4 chunks of 8 pairs ----
    #pragma unroll
    for (int it = 0; it < 2; it++) {
        const int idx = tid + it * 512;
        if (idx < 129 * 4) {
            const int r = idx >> 2, ch = idx & 3;
            const int i = i0 + r;
            if (i < SEQ) {
                const size_t base = (size_t)(b * SEQ + h * HD + (i >> 4)) * KP + ((i & 15) << 5) + ch * 8;
                *(uint4*)&sm->Qh[r][ch * 8]     = *(const uint4*)(g_Qh + base);
                *(uint4*)&sm->Qh[r][ch * 8 + 4] = *(const uint4*)(g_Qh + base + 4);
                *(uint4*)&sm->Ql[r][ch * 8]     = *(const uint4*)(g_Ql + base);
                *(uint4*)&sm->Ql[r][ch * 8 + 4] = *(const uint4*)(g_Ql + base + 4);
            } else {
                const uint4 z = make_uint4(0, 0, 0, 0);
                *(uint4*)&sm->Qh[r][ch * 8] = z; *(uint4*)&sm->Qh[r][ch * 8 + 4] = z;
                *(uint4*)&sm->Ql[r][ch * 8] = z; *(uint4*)&sm->Ql[r][ch * 8 + 4] = z;
            }
        }
    }

    float accO[4][4] = {};
    float m0 = -1e30f, m1 = -1e30f, l0 = 0.f, l1 = 0.f;
    const float* kbase = g_K + (size_t)(b * SEQ + h * HD) * DM;

    for (int jt = 0; jt < 8; jt++) {
        const int j0 = jt << 7;
        const int delta = j0 - i0;
        float accS[8][4] = {};

        // ---- relative-bias phases (Q pre-scaled; bias inherits 1/8) ----
        #pragma unroll 1
        for (int band = 0; band < 2; band++) {
            if (band == 0 && delta > 0) continue;
            if (band == 1 && delta < 0) continue;
            const int ebase = (band == 0) ? (895 + delta) : (delta - 130);
            #pragma unroll 1
            for (int half = 0; half < 2; half++) {
                if (band == 1 && half == 0 && delta < 128) continue;
                {   // load Er window half (packed hi copy)
                    const int r = tid >> 2, ch = tid & 3;
                    const int er = ebase + half * 128 + r;
                    if (er >= 0 && er < SEQ) {
                        const unsigned* pe = g_Eh + (size_t)er * 32 + ch * 8;
                        *(uint4*)&sm->Eh[r][ch * 8]     = *(const uint4*)pe;
                        *(uint4*)&sm->Eh[r][ch * 8 + 4] = *(const uint4*)(pe + 4);
                    } else {
                        const uint4 z = make_uint4(0, 0, 0, 0);
                        *(uint4*)&sm->Eh[r][ch * 8] = z; *(uint4*)&sm->Eh[r][ch * 8 + 4] = z;
                    }
                }
                __syncthreads();
                const int arow = rg16 + band;
                #pragma unroll 1
                for (int nh = 0; nh < 2; nh++) {
                    float gacc[4][4] = {};
                    const unsigned (*Ehp)[36] = (const unsigned (*)[36])&sm->Eh[cg * 64 + nh * 32];
                    #pragma unroll
                    for (int pb = 0; pb < 32; pb += 8)
                        mma_k16_1<4, 36, 36>(gacc, sm->Qh, Ehp, arow, pb, lane);
                    #pragma unroll
                    for (int tn = 0; tn < 4; tn++) {
                        const int r = rg16 + qr, c = cg * 64 + nh * 32 + tn * 8 + qc * 2;
                        *(float2*)&sm->u.G[r][c]     = make_float2(gacc[tn][0], gacc[tn][1]);
                        *(float2*)&sm->u.G[r + 8][c] = make_float2(gacc[tn][2], gacc[tn][3]);
                    }
                }
                __syncthreads();
                #pragma unroll
                for (int tn = 0; tn < 8; tn++)
                    #pragma unroll
                    for (int k = 0; k < 4; k++) {
                        const int r = rg16 + qr + ((k >> 1) << 3);
                        const int jc = cg * 64 + tn * 8 + qc * 2 + (k & 1);
                        const int diff = jc - r;
                        const bool cond = (band == 0) ? (diff <= -delta) : (diff >= 2 - delta);
                        const int mm = 128 + diff - half * 128;
                        if (cond && mm >= 0 && mm < 128) accS[tn][k] += sm->u.G[r][mm];
                    }
            }
        }

        // ---- load K^T and V tiles ----
        #pragma unroll
        for (int it = 0; it < 2; it++) {
            const int idx = tid + it * 512;
            const int kp = idx & 31, cgl = idx >> 5;
            const float* p = kbase + (size_t)(2 * kp) * DM + j0 + cgl * 4;
            st_km2x4<36>(*(const float4*)p, *(const float4*)(p + DM), sm->Kh, sm->Kl, cgl * 4, kp);
        }
        #pragma unroll
        for (int it = 0; it < 2; it++) {
            const int idx = tid + it * 512;
            const int jp = idx & 63, cgl = idx >> 6;
            const float4 x0 = *(const float4*)(v_row(b, h, j0 + 2 * jp)     + cgl * 4);
            const float4 x1 = *(const float4*)(v_row(b, h, j0 + 2 * jp + 1) + cgl * 4);
            st_km2x4<68>(x0, x1, sm->Vh, sm->Vl, cgl * 4, jp);
        }
        __syncthreads();

        // ---- q @ k^T accumulate on top of rel (Q pre-scaled by 1/8) ----
        {
            const unsigned (*Khp)[36] = (const unsigned (*)[36])&sm->Kh[cg * 64];
            const unsigned (*Klp)[36] = (const unsigned (*)[36])&sm->Kl[cg * 64];
            #pragma unroll
            for (int pb = 0; pb < 32; pb += 8)
                mma_k16_3<8, 36, 36>(accS, sm->Qh, sm->Ql, Khp, Klp, rg16, pb, lane);
        }

        // ---- online softmax (logits = accS directly) ----
        float tm0 = -1e30f, tm1 = -1e30f;
        #pragma unroll
        for (int tn = 0; tn < 8; tn++) {
            tm0 = fmaxf(tm0, fmaxf(accS[tn][0], accS[tn][1]));
            tm1 = fmaxf(tm1, fmaxf(accS[tn][2], accS[tn][3]));
        }
        tm0 = fmaxf(tm0, __shfl_xor_sync(0xffffffffu, tm0, 1));
        tm0 = fmaxf(tm0, __shfl_xor_sync(0xffffffffu, tm0, 2));
        tm1 = fmaxf(tm1, __shfl_xor_sync(0xffffffffu, tm1, 1));
        tm1 = fmaxf(tm1, __shfl_xor_sync(0xffffffffu, tm1, 2));
        if (qc == 0) {
            sm->redmax[rg16 + qr][cg]     = tm0;
            sm->redmax[rg16 + qr + 8][cg] = tm1;
        }
        __syncthreads();
        const float cm0 = fmaxf(sm->redmax[rg16 + qr][0],     sm->redmax[rg16 + qr][1]);
        const float cm1 = fmaxf(sm->redmax[rg16 + qr + 8][0], sm->redmax[rg16 + qr + 8][1]);
        const float nm0 = fmaxf(m0, cm0), nm1 = fmaxf(m1, cm1);
        const float f0 = __expf(m0 - nm0), f1 = __expf(m1 - nm1);
        float s0 = 0.f, s1 = 0.f;
        #pragma unroll
        for (int tn = 0; tn < 8; tn++) {
            accS[tn][0] = __expf(accS[tn][0] - nm0); s0 += accS[tn][0];
            accS[tn][1] = __expf(accS[tn][1] - nm0); s0 += accS[tn][1];
            accS[tn][2] = __expf(accS[tn][2] - nm1); s1 += accS[tn][2];
            accS[tn][3] = __expf(accS[tn][3] - nm1); s1 += accS[tn][3];
        }
        s0 += __shfl_xor_sync(0xffffffffu, s0, 1); s0 += __shfl_xor_sync(0xffffffffu, s0, 2);
        s1 += __shfl_xor_sync(0xffffffffu, s1, 1); s1 += __shfl_xor_sync(0xffffffffu, s1, 2);
        if (qc == 0) {
            sm->redsum[rg16 + qr][cg]     = s0;
            sm->redsum[rg16 + qr + 8][cg] = s1;
        }

        // ---- write split-bf16 P operand ----
        #pragma unroll
        for (int tn = 0; tn < 8; tn++) {
            unsigned hh, ll;
            split2(make_float2(accS[tn][0], accS[tn][1]), hh, ll);
            sm->u.pp.Ph[rg16 + qr][cg * 32 + tn * 4 + qc] = hh;
            sm->u.pp.Pl[rg16 + qr][cg * 32 + tn * 4 + qc] = ll;
            split2(make_float2(accS[tn][2], accS[tn][3]), hh, ll);
            sm->u.pp.Ph[rg16 + qr + 8][cg * 32 + tn * 4 + qc] = hh;
            sm->u.pp.Pl[rg16 + qr + 8][cg * 32 + tn * 4 + qc] = ll;
        }
        __syncthreads();

        const float cs0 = sm->redsum[rg16 + qr][0]     + sm->redsum[rg16 + qr][1];
        const float cs1 = sm->redsum[rg16 + qr + 8][0] + sm->redsum[rg16 + qr + 8][1];
        l0 = l0 * f0 + cs0; l1 = l1 * f1 + cs1; m0 = nm0; m1 = nm1;
        #pragma unroll
        for (int tn2 = 0; tn2 < 4; tn2++) {
            accO[tn2][0] *= f0; accO[tn2][1] *= f0;
            accO[tn2][2] *= f1; accO[tn2][3] *= f1;
        }

        // ---- accO += P @ V ----
        {
            const unsigned (*Vhp)[68] = (const unsigned (*)[68])&sm->Vh[cg * 32];
            const unsigned (*Vlp)[68] = (const unsigned (*)[68])&sm->Vl[cg * 32];
            #pragma unroll
            for (int pb = 0; pb < 64; pb += 8)
                mma_k16_3<4, 68, 68>(accO, sm->u.pp.Ph, sm->u.pp.Pl, Vhp, Vlp, rg16, pb, lane);
        }
    }

    // ---- epilogue: normalize, pack split-bf16, write O ----
    const float inv0 = 1.f / l0, inv1 = 1.f / l1;
    #pragma unroll
    for (int tn2 = 0; tn2 < 4; tn2++) {
        const int r = i0 + rg16 + qr;
        const int pidx = h * 32 + cg * 16 + tn2 * 4 + qc;
        unsigned hh, ll;
        split2(make_float2(accO[tn2][0] * inv0, accO[tn2][1] * inv0), hh, ll);
        g_Oh[(size_t)(b * SEQ + r) * KP + pidx] = hh;
        g_Ol[(size_t)(b * SEQ + r) * KP + pidx] = ll;
        split2(make_float2(accO[tn2][2] * inv1, accO[tn2][3] * inv1), hh, ll);
        g_Oh[(size_t)(b * SEQ + r + 8) * KP + pidx] = hh;
        g_Ol[(size_t)(b * SEQ + r + 8) * KP + pidx] = ll;
    }
}

// ---------------- launch ----------------
extern "C" void kernel_launch(void* const* d_in, const int* in_sizes, int n_in,
                              void* d_out, int out_size)
{
    const float* query = (const float*)d_in[0];
    const float* key   = (const float*)d_in[1];
    const float* value = (const float*)d_in[2];
    const float* WQ    = (const float*)d_in[3];
    const float* WK    = (const float*)d_in[4];
    const float* WV    = (const float*)d_in[5];
    const float* Er    = (const float*)d_in[6];
    const float* WM    = (const float*)d_in[7];
    float* out = (float*)d_out;

    static bool init = false;
    if (!init) {
        init = true;
        cudaFuncSetAttribute(flash_kernel, cudaFuncAttributeMaxDynamicSharedMemorySize,
                             (int)sizeof(FSmem));
        cudaFuncSetAttribute(gemm_qkv, cudaFuncAttributeMaxDynamicSharedMemorySize,
                             (int)sizeof(GSmem));
        cudaFuncSetAttribute(gemm_merge, cudaFuncAttributeMaxDynamicSharedMemorySize,
                             (int)sizeof(GSmem));
    }

    const int IN8 = MTOK * DM / 8;          // 524288

    pack_rm3<<<dim3(IN8 / 256, 3), 256>>>(query, key, value);
    pack_er<<<(SEQ * HD / 8) / 256, 256>>>(Er, SEQ * HD / 8);
    pack_cm4<<<dim3(16, 16, 4), 256>>>(WQ, WK, WV, WM);

    gemm_qkv<<<dim3(DM / 128, MTOK / 128, 3), 256, sizeof(GSmem)>>>();
    flash_kernel<<<dim3(SEQ / 128, BH), dim3(512), sizeof(FSmem)>>>();
    gemm_merge<<<dim3(DM / 128, MTOK / 128), 256, sizeof(GSmem)>>>(out);
}

// round 13
// speedup vs baseline: 1.4527x; 1.0607x over previous
#include <cuda_runtime.h>
#include <cuda_bf16.h>

#define BATCH 4
#define SEQ   1024
#define DM    1024
#define HEADS 16
#define HD    64
#define BH    (BATCH*HEADS)
#define MTOK  (BATCH*SEQ)          // 4096
#define KP    (DM/2)               // 512 packed pairs per row
#define OFFIN ((unsigned)MTOK*KP)
#define WOFF  ((unsigned)DM*KP)

// ---------------- scratch (device globals; no allocs allowed) ----------------
__device__ unsigned g_inh[3u*MTOK*KP], g_inl[3u*MTOK*KP];   // packed inputs (q,k,v)
__device__ unsigned g_wh[4u*DM*KP],   g_wl[4u*DM*KP];       // packed weights (col-major)
__device__ unsigned g_Qh[MTOK*KP],    g_Ql[MTOK*KP];        // packed Q projection (pre-scaled by 1/8)
__device__ float    g_K[MTOK*DM],     g_V[MTOK*DM];         // fp32 K,V projections
__device__ unsigned g_Kph[(size_t)BH*SEQ*32], g_Kpl[(size_t)BH*SEQ*32];  // K^T packed: [(bh*1024+j)*32+kp]
__device__ unsigned g_Vph[(size_t)BH*HD*512], g_Vpl[(size_t)BH*HD*512];  // V packed:  [(bh*64+dd)*512+jp]
__device__ unsigned g_Oh[MTOK*KP],    g_Ol[MTOK*KP];        // packed attention out
__device__ unsigned g_Eh[SEQ*(HD/2)];                       // packed Er (hi only)

// ---------------- helpers ----------------
__device__ __forceinline__ void split2(float2 v, unsigned &h, unsigned &l) {
    __nv_bfloat162 bh = __float22bfloat162_rn(v);
    float2 back = __bfloat1622float2(bh);
    __nv_bfloat162 bl = __float22bfloat162_rn(make_float2(v.x - back.x, v.y - back.y));
    h = *(unsigned*)&bh;
    l = *(unsigned*)&bl;
}

__device__ __forceinline__ unsigned sptr(const void* p) {
    return (unsigned)__cvta_generic_to_shared(p);
}

__device__ __forceinline__ void cpa16(unsigned dst, const void* src) {
    asm volatile("cp.async.cg.shared.global [%0], [%1], 16;" :: "r"(dst), "l"(src) : "memory");
}

__device__ __forceinline__ void ldsm4(unsigned r[4], unsigned a) {
    asm volatile("ldmatrix.sync.aligned.m8n8.x4.shared.b16 {%0,%1,%2,%3}, [%4];"
        : "=r"(r[0]), "=r"(r[1]), "=r"(r[2]), "=r"(r[3]) : "r"(a));
}

__device__ __forceinline__ void mma_bf16(float c[4], const unsigned a[4], const unsigned b[2]) {
    asm volatile(
        "mma.sync.aligned.m16n8k16.row.col.f32.bf16.bf16.f32 "
        "{%0,%1,%2,%3},{%4,%5,%6,%7},{%8,%9},{%0,%1,%2,%3};\n"
        : "+f"(c[0]), "+f"(c[1]), "+f"(c[2]), "+f"(c[3])
        : "r"(a[0]), "r"(a[1]), "r"(a[2]), "r"(a[3]), "r"(b[0]), "r"(b[1]));
}

// one k16 slab (pair base pb), TN n8-tiles (TN even), 3-term split MMA, ldmatrix feeds.
template<int TN, int PA, int PB>
__device__ __forceinline__ void mma_k16_3(float (*acc)[4],
    const unsigned (*Ah)[PA], const unsigned (*Al)[PA],
    const unsigned (*Bh)[PB], const unsigned (*Bl)[PB],
    int arow, int pb, int lane)
{
    const int ar = arow + (lane & 15);
    const int ac = pb + ((lane >> 4) << 2);
    unsigned ah[4], al[4];
    ldsm4(ah, sptr(&Ah[ar][ac]));
    ldsm4(al, sptr(&Al[ar][ac]));
    const int br = (lane & 7) + ((lane & 16) >> 1);
    const int bc = pb + ((lane & 8) >> 1);
    #pragma unroll
    for (int t2 = 0; t2 < TN / 2; t2++) {
        unsigned bh[4], bl[4];
        ldsm4(bh, sptr(&Bh[t2 * 16 + br][bc]));
        ldsm4(bl, sptr(&Bl[t2 * 16 + br][bc]));
        mma_bf16(acc[2 * t2],     ah, &bh[0]);
        mma_bf16(acc[2 * t2],     al, &bh[0]);
        mma_bf16(acc[2 * t2],     ah, &bl[0]);
        mma_bf16(acc[2 * t2 + 1], ah, &bh[2]);
        mma_bf16(acc[2 * t2 + 1], al, &bh[2]);
        mma_bf16(acc[2 * t2 + 1], ah, &bl[2]);
    }
}

// hi-only slab (bias GEMM): 1 MMA per n8 tile
template<int TN, int PA, int PB>
__device__ __forceinline__ void mma_k16_1(float (*acc)[4],
    const unsigned (*Ah)[PA], const unsigned (*Bh)[PB],
    int arow, int pb, int lane)
{
    const int ar = arow + (lane & 15);
    const int ac = pb + ((lane >> 4) << 2);
    unsigned ah[4];
    ldsm4(ah, sptr(&Ah[ar][ac]));
    const int br = (lane & 7) + ((lane & 16) >> 1);
    const int bc = pb + ((lane & 8) >> 1);
    #pragma unroll
    for (int t2 = 0; t2 < TN / 2; t2++) {
        unsigned bh[4];
        ldsm4(bh, sptr(&Bh[t2 * 16 + br][bc]));
        mma_bf16(acc[2 * t2],     ah, &bh[0]);
        mma_bf16(acc[2 * t2 + 1], ah, &bh[2]);
    }
}

// ==================== pack kernels ====================
__global__ __launch_bounds__(256) void pack_rm3(const float* __restrict__ s0,
                                                const float* __restrict__ s1,
                                                const float* __restrict__ s2)
{
    const int z = blockIdx.y;
    const float* src = (z == 0) ? s0 : (z == 1) ? s1 : s2;
    unsigned* dh = g_inh + (unsigned)z * OFFIN;
    unsigned* dl = g_inl + (unsigned)z * OFFIN;
    const int i = blockIdx.x * 256 + threadIdx.x;
    const float4 a = ((const float4*)src)[2 * i], b = ((const float4*)src)[2 * i + 1];
    unsigned h0, l0, h1, l1, h2, l2, h3, l3;
    split2(make_float2(a.x, a.y), h0, l0);
    split2(make_float2(a.z, a.w), h1, l1);
    split2(make_float2(b.x, b.y), h2, l2);
    split2(make_float2(b.z, b.w), h3, l3);
    ((uint4*)dh)[i] = make_uint4(h0, h1, h2, h3);
    ((uint4*)dl)[i] = make_uint4(l0, l1, l2, l3);
}

__global__ __launch_bounds__(256) void pack_er(const float* __restrict__ Er, int n8)
{
    const int i = blockIdx.x * 256 + threadIdx.x;
    if (i < n8) {
        const float4 a = ((const float4*)Er)[2 * i], b = ((const float4*)Er)[2 * i + 1];
        unsigned h0, l0, h1, l1, h2, l2, h3, l3;
        split2(make_float2(a.x, a.y), h0, l0);
        split2(make_float2(a.z, a.w), h1, l1);
        split2(make_float2(b.x, b.y), h2, l2);
        split2(make_float2(b.z, b.w), h3, l3);
        ((uint4*)g_Eh)[i] = make_uint4(h0, h1, h2, h3);
    }
}

__global__ __launch_bounds__(256) void pack_cm4(const float* __restrict__ W0,
                                                const float* __restrict__ W1,
                                                const float* __restrict__ W2,
                                                const float* __restrict__ W3)
{
    __shared__ float s[64][68];   // pitch 68: float4 stores stay 16B-aligned
    const int z = blockIdx.z;
    const float* W = (z == 0) ? W0 : (z == 1) ? W1 : (z == 2) ? W2 : W3;
    unsigned* dh = g_wh + (unsigned)z * WOFF;
    unsigned* dl = g_wl + (unsigned)z * WOFF;
    const int tid = threadIdx.x;
    const int k0 = blockIdx.y * 64, c0 = blockIdx.x * 64;
    #pragma unroll
    for (int it = 0; it < 4; it++) {
        const int idx = tid + it * 256;
        const int kr = idx >> 4, cc = (idx & 15) * 4;
        *(float4*)&s[kr][cc] = *(const float4*)(W + (size_t)(k0 + kr) * DM + c0 + cc);
    }
    __syncthreads();
    const int c = tid >> 2, ch = tid & 3;
    unsigned h[8], l[8];
    #pragma unroll
    for (int p = 0; p < 8; p++) {
        const int kp = ch * 8 + p;
        split2(make_float2(s[2 * kp][c], s[2 * kp + 1][c]), h[p], l[p]);
    }
    unsigned* oh = dh + (size_t)(c0 + c) * KP + (k0 >> 1) + ch * 8;
    unsigned* ol = dl + (size_t)(c0 + c) * KP + (k0 >> 1) + ch * 8;
    *(uint4*)oh       = make_uint4(h[0], h[1], h[2], h[3]);
    *(uint4*)(oh + 4) = make_uint4(h[4], h[5], h[6], h[7]);
    *(uint4*)ol       = make_uint4(l[0], l[1], l[2], l[3]);
    *(uint4*)(ol + 4) = make_uint4(l[4], l[5], l[6], l[7]);
}

// ==================== repack K/V into flash-native packed layouts ====================
// K^T: g_Kp[(bh*1024 + j)*32 + kp] = pair(K[dd=2kp][j], K[dd=2kp+1][j])
__global__ __launch_bounds__(256) void repack_k()
{
    __shared__ float s[64][132];
    const int bh = blockIdx.y, j0 = blockIdx.x * 128;
    const size_t rbase = (size_t)((bh >> 4) * 1024 + (bh & 15) * 64);
    const int tid = threadIdx.x;
    {
        const int r = tid >> 2, q = tid & 3;
        #pragma unroll
        for (int i = 0; i < 8; i++) {
            const int c = q * 32 + i * 4;
            *(float4*)&s[r][c] = *(const float4*)(g_K + (rbase + r) * DM + j0 + c);
        }
    }
    __syncthreads();
    const int lane = tid & 31, w = tid >> 5;
    for (int jj = w; jj < 128; jj += 8) {
        unsigned h, l;
        split2(make_float2(s[2 * lane][jj], s[2 * lane + 1][jj]), h, l);
        const size_t o = ((size_t)bh * 1024 + j0 + jj) * 32 + lane;
        g_Kph[o] = h; g_Kpl[o] = l;
    }
}

// V: g_Vp[(bh*64 + dd)*512 + jp] = pair(v[j=2jp][dd], v[j=2jp+1][dd])
// where v[j][dd] = g_V[rbase + (j>>4)][(j&15)*64 + dd]
__global__ __launch_bounds__(256) void repack_v()
{
    __shared__ float s[8][1024];
    const int bh = blockIdx.y, rg = blockIdx.x;     // 8 proj rows per block
    const size_t rbase = (size_t)((bh >> 4) * 1024 + (bh & 15) * 64) + rg * 8;
    const int tid = threadIdx.x;
    {
        const int r = tid >> 5, q = tid & 31;
        #pragma unroll
        for (int i = 0; i < 8; i++) {
            const int c = q * 4 + i * 128;
            *(float4*)&s[r][c] = *(const float4*)(g_V + (rbase + r) * DM + c);
        }
    }
    __syncthreads();
    const int lane = tid & 31, w = tid >> 5;
    const int jpl = lane & 7, ddl = lane >> 3;
    for (int it = w; it < 128; it += 8) {           // it = rr*16 + ddg
        const int rr = it >> 4, ddg = it & 15;
        const int dd = ddg * 4 + ddl;
        unsigned h, l;
        split2(make_float2(s[rr][2 * jpl * 64 + dd], s[rr][(2 * jpl + 1) * 64 + dd]), h, l);
        const int R = rg * 8 + rr;
        const size_t o = ((size_t)bh * 64 + dd) * 512 + R * 8 + jpl;
        g_Vph[o] = h; g_Vpl[o] = l;
    }
}

// ==================== packed GEMM: 4-stage cp.async ring, BK=16 ====================
struct GSmem { unsigned A[4][2][128][12]; unsigned B[4][2][128][12]; };   // 96 KB

__device__ __forceinline__ void mma16p(const unsigned (*Ah)[12], const unsigned (*Al)[12],
                                       const unsigned (*Bh)[12], const unsigned (*Bl)[12],
                                       float (*acc)[4][4], int warp_m, int warp_n, int lane) {
    const int arl = lane & 15, acl = (lane >> 4) << 2;
    const int brl = (lane & 7) + ((lane & 16) >> 1), bcl = (lane & 8) >> 1;
    unsigned ah[4][4], al[4][4], bh[2][4], bl[2][4];
    #pragma unroll
    for (int tm = 0; tm < 4; tm++) {
        ldsm4(ah[tm], sptr(&Ah[warp_m + tm * 16 + arl][acl]));
        ldsm4(al[tm], sptr(&Al[warp_m + tm * 16 + arl][acl]));
    }
    #pragma unroll
    for (int t2 = 0; t2 < 2; t2++) {
        ldsm4(bh[t2], sptr(&Bh[warp_n + t2 * 16 + brl][bcl]));
        ldsm4(bl[t2], sptr(&Bl[warp_n + t2 * 16 + brl][bcl]));
    }
    #pragma unroll
    for (int tm = 0; tm < 4; tm++)
        #pragma unroll
        for (int t2 = 0; t2 < 2; t2++) {
            mma_bf16(acc[tm][2 * t2],     ah[tm], &bh[t2][0]);
            mma_bf16(acc[tm][2 * t2],     al[tm], &bh[t2][0]);
            mma_bf16(acc[tm][2 * t2],     ah[tm], &bl[t2][0]);
            mma_bf16(acc[tm][2 * t2 + 1], ah[tm], &bh[t2][2]);
            mma_bf16(acc[tm][2 * t2 + 1], al[tm], &bh[t2][2]);
            mma_bf16(acc[tm][2 * t2 + 1], ah[tm], &bl[t2][2]);
        }
}

__device__ __forceinline__ void gemm_body(
    const unsigned* Agh, const unsigned* Agl,
    const unsigned* Bgh, const unsigned* Bgl,
    float* Cf, unsigned* Ch, unsigned* Cl, float cscale,
    GSmem* sm, int m0, int n0)
{
    const int tid = threadIdx.x, lane = tid & 31, w = tid >> 5;
    const int warp_m = (w >> 2) * 64, warp_n = (w & 3) * 32;
    const int lrow = tid >> 1, loff = (tid & 1) << 2;
    const unsigned* Ash = Agh + (size_t)(m0 + lrow) * KP + loff;
    const unsigned* Asl = Agl + (size_t)(m0 + lrow) * KP + loff;
    const unsigned* Bsh = Bgh + (size_t)(n0 + lrow) * KP + loff;
    const unsigned* Bsl = Bgl + (size_t)(n0 + lrow) * KP + loff;

    auto load = [&](int s, int st) {
        const int kp0 = s << 3;
        cpa16(sptr(&sm->A[st][0][lrow][loff]), Ash + kp0);
        cpa16(sptr(&sm->A[st][1][lrow][loff]), Asl + kp0);
        cpa16(sptr(&sm->B[st][0][lrow][loff]), Bsh + kp0);
        cpa16(sptr(&sm->B[st][1][lrow][loff]), Bsl + kp0);
        asm volatile("cp.async.commit_group;" ::: "memory");
    };

    float acc[4][4][4] = {};
    load(0, 0); load(1, 1); load(2, 2);
    for (int s = 0; s < 64; s++) {
        const int st = s & 3;
        asm volatile("cp.async.wait_group 2;" ::: "memory");
        __syncthreads();
        if (s < 61) load(s + 3, (s + 3) & 3);
        else        asm volatile("cp.async.commit_group;" ::: "memory");
        mma16p(sm->A[st][0], sm->A[st][1], sm->B[st][0], sm->B[st][1],
               acc, warp_m, warp_n, lane);
    }

    const int qr = lane >> 2, qc = lane & 3;
    if (Cf) {
        #pragma unroll
        for (int tm = 0; tm < 4; tm++)
            #pragma unroll
            for (int tn = 0; tn < 4; tn++) {
                const int r = m0 + warp_m + tm * 16 + qr;
                const int cN = n0 + warp_n + tn * 8 + qc * 2;
                *(float2*)(Cf + (size_t)r * DM + cN)       = make_float2(acc[tm][tn][0], acc[tm][tn][1]);
                *(float2*)(Cf + (size_t)(r + 8) * DM + cN) = make_float2(acc[tm][tn][2], acc[tm][tn][3]);
            }
    } else {
        #pragma unroll
        for (int tm = 0; tm < 4; tm++)
            #pragma unroll
            for (int tn = 0; tn < 4; tn++) {
                const int r = m0 + warp_m + tm * 16 + qr;
                const int pidx = ((n0 + warp_n) >> 1) + tn * 4 + qc;
                unsigned hh, ll;
                split2(make_float2(acc[tm][tn][0] * cscale, acc[tm][tn][1] * cscale), hh, ll);
                Ch[(size_t)r * KP + pidx] = hh; Cl[(size_t)r * KP + pidx] = ll;
                split2(make_float2(acc[tm][tn][2] * cscale, acc[tm][tn][3] * cscale), hh, ll);
                Ch[(size_t)(r + 8) * KP + pidx] = hh; Cl[(size_t)(r + 8) * KP + pidx] = ll;
            }
    }
}

__global__ __launch_bounds__(256, 2) void gemm_qkv()
{
    extern __shared__ char raw[];
    const int z = blockIdx.z;
    const unsigned* Agh = g_inh + (unsigned)z * OFFIN;
    const unsigned* Agl = g_inl + (unsigned)z * OFFIN;
    const unsigned* Bgh = g_wh + (unsigned)z * WOFF;
    const unsigned* Bgl = g_wl + (unsigned)z * WOFF;
    float* Cf = (z == 1) ? g_K : (z == 2) ? g_V : nullptr;
    gemm_body(Agh, Agl, Bgh, Bgl, Cf, g_Qh, g_Ql, 0.125f,
              (GSmem*)raw, blockIdx.y << 7, blockIdx.x << 7);
}

__global__ __launch_bounds__(256, 2) void gemm_merge(float* __restrict__ out)
{
    extern __shared__ char raw[];
    gemm_body(g_Oh, g_Ol, g_wh + 3u * WOFF, g_wl + 3u * WOFF, out, nullptr, nullptr, 1.f,
              (GSmem*)raw, blockIdx.y << 7, blockIdx.x << 7);
}

// ==================== fused flash attention with relative bias (512 threads) ====================
struct FSmem {
    unsigned Qh[129][36], Ql[129][36];   // Q rows i0..i0+128 (129 for the +1 shift), pre-scaled 1/8
    unsigned Kh[128][36], Kl[128][36];   // K^T tile: [j][dd-pair]  (prepacked)
    unsigned Eh[128][36];                // Er window (hi-only)
    unsigned Vh[64][68],  Vl[64][68];    // V tile: [dd][j-pair]    (prepacked)
    union {
        float G[128][132];                                 // rel-bias staging
        struct { unsigned Ph[128][68], Pl[128][68]; } pp;  // softmaxed P operand
    } u;
    float redmax[128][2];
    float redsum[128][2];
};

__global__ __launch_bounds__(512, 1) void flash_kernel()
{
    extern __shared__ char raw[];
    FSmem* sm = (FSmem*)raw;
    const int tid = threadIdx.x, lane = tid & 31, w = tid >> 5;   // 16 warps
    const int qr = lane >> 2, qc = lane & 3;
    const int rg = w & 7, cg = w >> 3;
    const int rg16 = rg << 4;
    const int bh = blockIdx.y, b = bh >> 4, h = bh & 15;
    const int i0 = blockIdx.x << 7;

    // ---- load Q (packed copy): 129 rows x 4 chunks of 8 pairs ----
    #pragma unroll
    for (int it = 0; it < 2; it++) {
        const int idx = tid + it * 512;
        if (idx < 129 * 4) {
            const int r = idx >> 2, ch = idx & 3;
            const int i = i0 + r;
            if (i < SEQ) {
                const size_t base = (size_t)(b * SEQ + h * HD + (i >> 4)) * KP + ((i & 15) << 5) + ch * 8;
                *(uint4*)&sm->Qh[r][ch * 8]     = *(const uint4*)(g_Qh + base);
                *(uint4*)&sm->Qh[r][ch * 8 + 4] = *(const uint4*)(g_Qh + base + 4);
                *(uint4*)&sm->Ql[r][ch * 8]     = *(const uint4*)(g_Ql + base);
                *(uint4*)&sm->Ql[r][ch * 8 + 4] = *(const uint4*)(g_Ql + base + 4);
            } else {
                const uint4 z = make_uint4(0, 0, 0, 0);
                *(uint4*)&sm->Qh[r][ch * 8] = z; *(uint4*)&sm->Qh[r][ch * 8 + 4] = z;
                *(uint4*)&sm->Ql[r][ch * 8] = z; *(uint4*)&sm->Ql[r][ch * 8 + 4] = z;
            }
        }
    }

    float accO[4][4] = {};
    float m0 = -1e30f, m1 = -1e30f, l0 = 0.f, l1 = 0.f;
    const unsigned* kbh = g_Kph + (size_t)bh * 1024 * 32;
    const unsigned* kbl = g_Kpl + (size_t)bh * 1024 * 32;
    const unsigned* vbh = g_Vph + (size_t)bh * 64 * 512;
    const unsigned* vbl = g_Vpl + (size_t)bh * 64 * 512;

    for (int jt = 0; jt < 8; jt++) {
        const int j0 = jt << 7;
        const int delta = j0 - i0;
        float accS[8][4] = {};

        // ---- ensure prior tile's K/V LDSM reads are done, then prefetch K/V via cp.async ----
        __syncthreads();
        #pragma unroll
        for (int it = 0; it < 2; it++) {
            const int idx = tid + it * 512;            // 0..1023
            const int r = idx >> 3, o = (idx & 7) * 4;
            cpa16(sptr(&sm->Kh[r][o]), kbh + (size_t)(j0 + r) * 32 + o);
            cpa16(sptr(&sm->Kl[r][o]), kbl + (size_t)(j0 + r) * 32 + o);
        }
        #pragma unroll
        for (int it = 0; it < 2; it++) {
            const int idx = tid + it * 512;
            const int dd = idx >> 4, o = (idx & 15) * 4;
            cpa16(sptr(&sm->Vh[dd][o]), vbh + (size_t)dd * 512 + (j0 >> 1) + o);
            cpa16(sptr(&sm->Vl[dd][o]), vbl + (size_t)dd * 512 + (j0 >> 1) + o);
        }
        asm volatile("cp.async.commit_group;" ::: "memory");

        // ---- relative-bias phases (Q pre-scaled; bias inherits 1/8) ----
        #pragma unroll 1
        for (int band = 0; band < 2; band++) {
            if (band == 0 && delta > 0) continue;
            if (band == 1 && delta < 0) continue;
            const int ebase = (band == 0) ? (895 + delta) : (delta - 130);
            #pragma unroll 1
            for (int half = 0; half < 2; half++) {
                if (band == 1 && half == 0 && delta < 128) continue;
                {   // load Er window half (packed hi copy)
                    const int r = tid >> 2, ch = tid & 3;
                    const int er = ebase + half * 128 + r;
                    if (er >= 0 && er < SEQ) {
                        const unsigned* pe = g_Eh + (size_t)er * 32 + ch * 8;
                        *(uint4*)&sm->Eh[r][ch * 8]     = *(const uint4*)pe;
                        *(uint4*)&sm->Eh[r][ch * 8 + 4] = *(const uint4*)(pe + 4);
                    } else {
                        const uint4 z = make_uint4(0, 0, 0, 0);
                        *(uint4*)&sm->Eh[r][ch * 8] = z; *(uint4*)&sm->Eh[r][ch * 8 + 4] = z;
                    }
                }
                __syncthreads();
                const int arow = rg16 + band;
                #pragma unroll 1
                for (int nh = 0; nh < 2; nh++) {
                    float gacc[4][4] = {};
                    const unsigned (*Ehp)[36] = (const unsigned (*)[36])&sm->Eh[cg * 64 + nh * 32];
                    #pragma unroll
                    for (int pb = 0; pb < 32; pb += 8)
                        mma_k16_1<4, 36, 36>(gacc, sm->Qh, Ehp, arow, pb, lane);
                    #pragma unroll
                    for (int tn = 0; tn < 4; tn++) {
                        const int r = rg16 + qr, c = cg * 64 + nh * 32 + tn * 8 + qc * 2;
                        *(float2*)&sm->u.G[r][c]     = make_float2(gacc[tn][0], gacc[tn][1]);
                        *(float2*)&sm->u.G[r + 8][c] = make_float2(gacc[tn][2], gacc[tn][3]);
                    }
                }
                __syncthreads();
                // gather with exec-constant bounds [lo,hi] on mm
                const int lo = (band == 0) ? 0 : max(130 - delta - 128 * half, 0);
                const int hi = (band == 0) ? min(128 - delta - 128 * half, 127) : 127;
                const int span = hi - lo;
                const int base0 = cg * 64 + qc * 2 - (rg16 + qr) + 128 - 128 * half;
                #pragma unroll
                for (int tn = 0; tn < 8; tn++)
                    #pragma unroll
                    for (int k = 0; k < 4; k++) {
                        const int mm = base0 - ((k >> 1) << 3) + tn * 8 + (k & 1);
                        if ((unsigned)(mm - lo) <= (unsigned)span)
                            accS[tn][k] += sm->u.G[rg16 + qr + ((k >> 1) << 3)][mm];
                    }
            }
        }

        // ---- wait for K/V prefetch ----
        asm volatile("cp.async.wait_group 0;" ::: "memory");
        __syncthreads();

        // ---- q @ k^T accumulate on top of rel (Q pre-scaled by 1/8) ----
        {
            const unsigned (*Khp)[36] = (const unsigned (*)[36])&sm->Kh[cg * 64];
            const unsigned (*Klp)[36] = (const unsigned (*)[36])&sm->Kl[cg * 64];
            #pragma unroll
            for (int pb = 0; pb < 32; pb += 8)
                mma_k16_3<8, 36, 36>(accS, sm->Qh, sm->Ql, Khp, Klp, rg16, pb, lane);
        }

        // ---- online softmax ----
        float tm0 = -1e30f, tm1 = -1e30f;
        #pragma unroll
        for (int tn = 0; tn < 8; tn++) {
            tm0 = fmaxf(tm0, fmaxf(accS[tn][0], accS[tn][1]));
            tm1 = fmaxf(tm1, fmaxf(accS[tn][2], accS[tn][3]));
        }
        tm0 = fmaxf(tm0, __shfl_xor_sync(0xffffffffu, tm0, 1));
        tm0 = fmaxf(tm0, __shfl_xor_sync(0xffffffffu, tm0, 2));
        tm1 = fmaxf(tm1, __shfl_xor_sync(0xffffffffu, tm1, 1));
        tm1 = fmaxf(tm1, __shfl_xor_sync(0xffffffffu, tm1, 2));
        if (qc == 0) {
            sm->redmax[rg16 + qr][cg]     = tm0;
            sm->redmax[rg16 + qr + 8][cg] = tm1;
        }
        __syncthreads();
        const float cm0 = fmaxf(sm->redmax[rg16 + qr][0],     sm->redmax[rg16 + qr][1]);
        const float cm1 = fmaxf(sm->redmax[rg16 + qr + 8][0], sm->redmax[rg16 + qr + 8][1]);
        const float nm0 = fmaxf(m0, cm0), nm1 = fmaxf(m1, cm1);
        const float f0 = __expf(m0 - nm0), f1 = __expf(m1 - nm1);
        float s0 = 0.f, s1 = 0.f;
        #pragma unroll
        for (int tn = 0; tn < 8; tn++) {
            accS[tn][0] = __expf(accS[tn][0] - nm0); s0 += accS[tn][0];
            accS[tn][1] = __expf(accS[tn][1] - nm0); s0 += accS[tn][1];
            accS[tn][2] = __expf(accS[tn][2] - nm1); s1 += accS[tn][2];
            accS[tn][3] = __expf(accS[tn][3] - nm1); s1 += accS[tn][3];
        }
        s0 += __shfl_xor_sync(0xffffffffu, s0, 1); s0 += __shfl_xor_sync(0xffffffffu, s0, 2);
        s1 += __shfl_xor_sync(0xffffffffu, s1, 1); s1 += __shfl_xor_sync(0xffffffffu, s1, 2);
        if (qc == 0) {
            sm->redsum[rg16 + qr][cg]     = s0;
            sm->redsum[rg16 + qr + 8][cg] = s1;
        }

        // ---- write split-bf16 P operand ----
        #pragma unroll
        for (int tn = 0; tn < 8; tn++) {
            unsigned hh, ll;
            split2(make_float2(accS[tn][0], accS[tn][1]), hh, ll);
            sm->u.pp.Ph[rg16 + qr][cg * 32 + tn * 4 + qc] = hh;
            sm->u.pp.Pl[rg16 + qr][cg * 32 + tn * 4 + qc] = ll;
            split2(make_float2(accS[tn][2], accS[tn][3]), hh, ll);
            sm->u.pp.Ph[rg16 + qr + 8][cg * 32 + tn * 4 + qc] = hh;
            sm->u.pp.Pl[rg16 + qr + 8][cg * 32 + tn * 4 + qc] = ll;
        }
        __syncthreads();

        const float cs0 = sm->redsum[rg16 + qr][0]     + sm->redsum[rg16 + qr][1];
        const float cs1 = sm->redsum[rg16 + qr + 8][0] + sm->redsum[rg16 + qr + 8][1];
        l0 = l0 * f0 + cs0; l1 = l1 * f1 + cs1; m0 = nm0; m1 = nm1;
        #pragma unroll
        for (int tn2 = 0; tn2 < 4; tn2++) {
            accO[tn2][0] *= f0; accO[tn2][1] *= f0;
            accO[tn2][2] *= f1; accO[tn2][3] *= f1;
        }

        // ---- accO += P @ V ----
        {
            const unsigned (*Vhp)[68] = (const unsigned (*)[68])&sm->Vh[cg * 32];
            const unsigned (*Vlp)[68] = (const unsigned (*)[68])&sm->Vl[cg * 32];
            #pragma unroll
            for (int pb = 0; pb < 64; pb += 8)
                mma_k16_3<4, 68, 68>(accO, sm->u.pp.Ph, sm->u.pp.Pl, Vhp, Vlp, rg16, pb, lane);
        }
    }

    // ---- epilogue: normalize, pack split-bf16, write O ----
    const float inv0 = 1.f / l0, inv1 = 1.f / l1;
    #pragma unroll
    for (int tn2 = 0; tn2 < 4; tn2++) {
        const int r = i0 + rg16 + qr;
        const int pidx = h * 32 + cg * 16 + tn2 * 4 + qc;
        unsigned hh, ll;
        split2(make_float2(accO[tn2][0] * inv0, accO[tn2][1] * inv0), hh, ll);
        g_Oh[(size_t)(b * SEQ + r) * KP + pidx] = hh;
        g_Ol[(size_t)(b * SEQ + r) * KP + pidx] = ll;
        split2(make_float2(accO[tn2][2] * inv1, accO[tn2][3] * inv1), hh, ll);
        g_Oh[(size_t)(b * SEQ + r + 8) * KP + pidx] = hh;
        g_Ol[(size_t)(b * SEQ + r + 8) * KP + pidx] = ll;
    }
}

// ---------------- launch ----------------
extern "C" void kernel_launch(void* const* d_in, const int* in_sizes, int n_in,
                              void* d_out, int out_size)
{
    const float* query = (const float*)d_in[0];
    const float* key   = (const float*)d_in[1];
    const float* value = (const float*)d_in[2];
    const float* WQ    = (const float*)d_in[3];
    const float* WK    = (const float*)d_in[4];
    const float* WV    = (const float*)d_in[5];
    const float* Er    = (const float*)d_in[6];
    const float* WM    = (const float*)d_in[7];
    float* out = (float*)d_out;

    static bool init = false;
    if (!init) {
        init = true;
        cudaFuncSetAttribute(flash_kernel, cudaFuncAttributeMaxDynamicSharedMemorySize,
                             (int)sizeof(FSmem));
        cudaFuncSetAttribute(gemm_qkv, cudaFuncAttributeMaxDynamicSharedMemorySize,
                             (int)sizeof(GSmem));
        cudaFuncSetAttribute(gemm_merge, cudaFuncAttributeMaxDynamicSharedMemorySize,
                             (int)sizeof(GSmem));
    }

    const int IN8 = MTOK * DM / 8;          // 524288

    pack_rm3<<<dim3(IN8 / 256, 3), 256>>>(query, key, value);
    pack_er<<<(SEQ * HD / 8) / 256, 256>>>(Er, SEQ * HD / 8);
    pack_cm4<<<dim3(16, 16, 4), 256>>>(WQ, WK, WV, WM);

    gemm_qkv<<<dim3(DM / 128, MTOK / 128, 3), 256, sizeof(GSmem)>>>();
    repack_k<<<dim3(8, BH), 256>>>();
    repack_v<<<dim3(8, BH), 256>>>();
    flash_kernel<<<dim3(SEQ / 128, BH), dim3(512), sizeof(FSmem)>>>();
    gemm_merge<<<dim3(DM / 128, MTOK / 128), 256, sizeof(GSmem)>>>(out);
}